// round 10
// baseline (speedup 1.0000x reference)
#include <cuda_runtime.h>
#include <cuda_bf16.h>
#include <math.h>
#include <stdint.h>

#define NP_MAX 50000
#define NP_PAD 50048
#define NHE_MAX 5000
#define DIN 128
#define CAPH 256
#define CAPP 64

// ---------------------------------------------------------------------------
// Device scratch (no allocations allowed)
// ---------------------------------------------------------------------------
__device__ float g_he_feat[NHE_MAX * DIN];       // 2.56 MB
__device__ float g_he_weighted[NHE_MAX * DIN];   // 2.56 MB
__device__ float g_cluster[NP_MAX * DIN];        // 25.6 MB
__device__ float g_h[NHE_MAX * 256];             // 5.12 MB (attn hidden)

// Split-bf16 activation images (written by GEMM epilogues, read as MMA A)
__device__ __align__(16) __nv_bfloat16 g_cat_hi[NP_PAD * 256];   // 25.6 MB
__device__ __align__(16) __nv_bfloat16 g_cat_lo[NP_PAD * 256];
__device__ __align__(16) __nv_bfloat16 g_t1_hi[NP_PAD * 256];
__device__ __align__(16) __nv_bfloat16 g_t1_lo[NP_PAD * 256];

// Bucketed edge lists (gather form of the two segment-sums)
__device__ int2 g_bktH[NHE_MAX * CAPH];          // {pid, w}  10.2 MB
__device__ int2 g_bktP[NP_MAX * CAPP];           // {hid, w}  25.6 MB
__device__ int g_cntH[NHE_MAX];
__device__ int g_cntP[NP_MAX];
__device__ int g_ovfH_cnt, g_ovfP_cnt;
__device__ int g_ovfH[800000];
__device__ int g_ovfP[800000];

// bf16 weight images, [n][k] row-major:
// 0: Wself | 1: Wclu | 2,3: Wf1 col0 ch0/1 | 4,5: Wf1 col1 ch0/1 | 6,7: Wf2 | 8,9: Wh1
__device__ __align__(16) __nv_bfloat16 g_wimg_hi[10][128 * 128];
__device__ __align__(16) __nv_bfloat16 g_wimg_lo[10][128 * 128];

__device__ __forceinline__ unsigned int packbf2(__nv_bfloat16 a, __nv_bfloat16 b) {
    return ((unsigned int)__bfloat16_as_ushort(b) << 16) | __bfloat16_as_ushort(a);
}

// ---------------------------------------------------------------------------
// mma.sync m16n8k16 bf16 (baseline PTX, HMMA on sm_103)
// ---------------------------------------------------------------------------
__device__ __forceinline__ void mma_bf16(float* d, const unsigned* a, const unsigned* b) {
    asm volatile(
        "mma.sync.aligned.m16n8k16.row.col.f32.bf16.bf16.f32 "
        "{%0,%1,%2,%3}, {%4,%5,%6,%7}, {%8,%9}, {%0,%1,%2,%3};"
        : "+f"(d[0]), "+f"(d[1]), "+f"(d[2]), "+f"(d[3])
        : "r"(a[0]), "r"(a[1]), "r"(a[2]), "r"(a[3]), "r"(b[0]), "r"(b[1]));
}

// SMEM: A hi/lo + B hi/lo, each [128][136] bf16 (stride 272 B, conflict-free)
#define STRB 272
#define OFF_AHI 0
#define OFF_ALO (128 * STRB)
#define OFF_BHI (2 * 128 * STRB)
#define OFF_BLO (3 * 128 * STRB)
#define TC_SMEM_BYTES (4 * 128 * STRB)   // 139264

// Stage fp32 A chunk -> bf16 hi/lo split into smem (used when A is fp32)
__device__ __forceinline__ void stage_A_f32(const float* __restrict__ A, int ldA,
                                            int row0, int nRows, int k0,
                                            char* sAhi, char* sAlo, int tid) {
#pragma unroll
    for (int i = 0; i < 16; i++) {
        int g = tid + 256 * i;
        int r = g >> 5, c4 = g & 31;
        int grow = row0 + r;
        float4 v = {0.f, 0.f, 0.f, 0.f};
        if (grow < nRows)
            v = __ldg((const float4*)(A + (size_t)grow * ldA + k0) + c4);
        __nv_bfloat16 h0 = __float2bfloat16(v.x), h1 = __float2bfloat16(v.y);
        __nv_bfloat16 h2 = __float2bfloat16(v.z), h3 = __float2bfloat16(v.w);
        __nv_bfloat16 l0 = __float2bfloat16(v.x - __bfloat162float(h0));
        __nv_bfloat16 l1 = __float2bfloat16(v.y - __bfloat162float(h1));
        __nv_bfloat16 l2 = __float2bfloat16(v.z - __bfloat162float(h2));
        __nv_bfloat16 l3 = __float2bfloat16(v.w - __bfloat162float(h3));
        uint2 hu, lu;
        hu.x = packbf2(h0, h1); hu.y = packbf2(h2, h3);
        lu.x = packbf2(l0, l1); lu.y = packbf2(l2, l3);
        int off = r * STRB + c4 * 8;
        *(uint2*)(sAhi + off) = hu;
        *(uint2*)(sAlo + off) = lu;
    }
}

// Stage pre-split bf16 A chunk (pure copy; ld row stride = 256 bf16)
__device__ __forceinline__ void stage_A_bf16(const __nv_bfloat16* __restrict__ hi,
                                             const __nv_bfloat16* __restrict__ lo,
                                             int row0, int k0,
                                             char* sAhi, char* sAlo, int tid) {
#pragma unroll
    for (int i = 0; i < 8; i++) {
        int idx = tid + 256 * i;            // 2048 uint4 = 128 rows x 256B
        int r = idx >> 4, kg = idx & 15;
        size_t gofs = (size_t)(row0 + r) * 256 + k0;
        uint4 h = __ldg((const uint4*)(hi + gofs) + kg);
        uint4 l = __ldg((const uint4*)(lo + gofs) + kg);
        *(uint4*)(sAhi + r * STRB + kg * 16) = h;
        *(uint4*)(sAlo + r * STRB + kg * 16) = l;
    }
}

__device__ __forceinline__ void copy_B(const __nv_bfloat16* hi, const __nv_bfloat16* lo,
                                       char* sBhi, char* sBlo, int tid) {
#pragma unroll
    for (int i = 0; i < 8; i++) {
        int idx = tid + 256 * i;
        int r = idx >> 4, kg = idx & 15;
        uint4 h = __ldg((const uint4*)hi + idx);
        uint4 l = __ldg((const uint4*)lo + idx);
        *(uint4*)(sBhi + r * STRB + kg * 16) = h;
        *(uint4*)(sBlo + r * STRB + kg * 16) = l;
    }
}

__device__ __forceinline__ void hmma_chunk(const char* sm, int warpM, int warpN,
                                           int lane, float acc[2][8][4]) {
    int qr = lane >> 2, qc = lane & 3;
    const char* sAhi = sm + OFF_AHI;
    const char* sAlo = sm + OFF_ALO;
    const char* sBhi = sm + OFF_BHI;
    const char* sBlo = sm + OFF_BLO;
#pragma unroll
    for (int ks = 0; ks < 8; ks++) {
        int k0 = ks * 16;
        unsigned ah[2][4], al[2][4];
#pragma unroll
        for (int mt = 0; mt < 2; mt++) {
            int r = warpM + mt * 16 + qr;
            int cb = (k0 + qc * 2) * 2;
            const char* p0 = sAhi + r * STRB + cb;
            const char* p1 = sAhi + (r + 8) * STRB + cb;
            ah[mt][0] = *(const unsigned*)p0;
            ah[mt][1] = *(const unsigned*)p1;
            ah[mt][2] = *(const unsigned*)(p0 + 16);
            ah[mt][3] = *(const unsigned*)(p1 + 16);
            const char* q0 = sAlo + r * STRB + cb;
            const char* q1 = sAlo + (r + 8) * STRB + cb;
            al[mt][0] = *(const unsigned*)q0;
            al[mt][1] = *(const unsigned*)q1;
            al[mt][2] = *(const unsigned*)(q0 + 16);
            al[mt][3] = *(const unsigned*)(q1 + 16);
        }
#pragma unroll
        for (int nt = 0; nt < 8; nt++) {
            int n = warpN + nt * 8 + qr;
            int cb = (k0 + qc * 2) * 2;
            unsigned bh[2], bl[2];
            const char* pb = sBhi + n * STRB + cb;
            bh[0] = *(const unsigned*)pb;
            bh[1] = *(const unsigned*)(pb + 16);
            const char* pl = sBlo + n * STRB + cb;
            bl[0] = *(const unsigned*)pl;
            bl[1] = *(const unsigned*)(pl + 16);
#pragma unroll
            for (int mt = 0; mt < 2; mt++) {
                mma_bf16(acc[mt][nt], ah[mt], bh);
                mma_bf16(acc[mt][nt], ah[mt], bl);
                mma_bf16(acc[mt][nt], al[mt], bh);
            }
        }
    }
}

// Epilogue to fp32 global (attn path)
__device__ __forceinline__ void epi_f32(const float acc[2][8][4],
                                        const float* __restrict__ bias,
                                        float* __restrict__ outBase, int ldOut,
                                        int row0, int nRows, bool relu,
                                        int warpM, int warpN, int lane) {
    int qr = lane >> 2, qc = lane & 3;
#pragma unroll
    for (int mt = 0; mt < 2; mt++) {
#pragma unroll
        for (int nt = 0; nt < 8; nt++) {
            int col = warpN + nt * 8 + qc * 2;
            float b0 = __ldg(bias + col), b1 = __ldg(bias + col + 1);
            int r0 = row0 + warpM + mt * 16 + qr;
#pragma unroll
            for (int half = 0; half < 2; half++) {
                int grow = r0 + half * 8;
                if (grow < nRows) {
                    float2 v;
                    v.x = acc[mt][nt][half * 2 + 0] + b0;
                    v.y = acc[mt][nt][half * 2 + 1] + b1;
                    if (relu) { v.x = fmaxf(v.x, 0.f); v.y = fmaxf(v.y, 0.f); }
                    *(float2*)(outBase + (size_t)grow * ldOut + col) = v;
                }
            }
        }
    }
}

// Epilogue to split-bf16 images (rows of 256, write at colOff + warp cols)
__device__ __forceinline__ void epi_bf16(const float acc[2][8][4],
                                         const float* __restrict__ bias,
                                         __nv_bfloat16* __restrict__ hiImg,
                                         __nv_bfloat16* __restrict__ loImg,
                                         int colOff, int row0, int nRows, bool relu,
                                         int warpM, int warpN, int lane) {
    int qr = lane >> 2, qc = lane & 3;
#pragma unroll
    for (int mt = 0; mt < 2; mt++) {
#pragma unroll
        for (int nt = 0; nt < 8; nt++) {
            int col = warpN + nt * 8 + qc * 2;
            float b0 = __ldg(bias + col), b1 = __ldg(bias + col + 1);
            int gcol = colOff + col;
            int r0 = row0 + warpM + mt * 16 + qr;
#pragma unroll
            for (int half = 0; half < 2; half++) {
                int grow = r0 + half * 8;
                if (grow < nRows) {
                    float vx = acc[mt][nt][half * 2 + 0] + b0;
                    float vy = acc[mt][nt][half * 2 + 1] + b1;
                    if (relu) { vx = fmaxf(vx, 0.f); vy = fmaxf(vy, 0.f); }
                    __nv_bfloat16 hx = __float2bfloat16(vx);
                    __nv_bfloat16 hy = __float2bfloat16(vy);
                    __nv_bfloat16 lx = __float2bfloat16(vx - __bfloat162float(hx));
                    __nv_bfloat16 ly = __float2bfloat16(vy - __bfloat162float(hy));
                    size_t o = (size_t)grow * 256 + gcol;
                    *(unsigned*)(hiImg + o) = packbf2(hx, hy);
                    *(unsigned*)(loImg + o) = packbf2(lx, ly);
                }
            }
        }
    }
}

// ---------------------------------------------------------------------------
// Setup kernels
// ---------------------------------------------------------------------------
__global__ void zero_counts_kernel() {
    int i = blockIdx.x * blockDim.x + threadIdx.x;
    if (i < NP_MAX) g_cntP[i] = 0;
    if (i < NHE_MAX) g_cntH[i] = 0;
    if (i == 0) { g_ovfH_cnt = 0; g_ovfP_cnt = 0; }
}

__global__ void prep_weights(const float* __restrict__ Wself,
                             const float* __restrict__ Wclu,
                             const float* __restrict__ Wf1,
                             const float* __restrict__ Wf2,
                             const float* __restrict__ Wh1) {
    int g = blockIdx.x * 256 + threadIdx.x;   // 163840 total
    int img = g >> 14;
    int e = g & 16383;
    int n = e >> 7, k = e & 127;
    float val;
    switch (img) {
        case 0: val = __ldg(Wself + k * 128 + n); break;
        case 1: val = __ldg(Wclu + k * 128 + n); break;
        case 2: val = __ldg(Wf1 + k * 256 + n); break;
        case 3: val = __ldg(Wf1 + (128 + k) * 256 + n); break;
        case 4: val = __ldg(Wf1 + k * 256 + 128 + n); break;
        case 5: val = __ldg(Wf1 + (128 + k) * 256 + 128 + n); break;
        case 6: val = __ldg(Wf2 + k * 128 + n); break;
        case 7: val = __ldg(Wf2 + (128 + k) * 128 + n); break;
        case 8: val = __ldg(Wh1 + ((n >> 6) * 128 + k) * 64 + (n & 63)); break;
        default: val = __ldg(Wh1 + ((2 + (n >> 6)) * 128 + k) * 64 + (n & 63)); break;
    }
    __nv_bfloat16 hi = __float2bfloat16(val);
    __nv_bfloat16 lo = __float2bfloat16(val - __bfloat162float(hi));
    g_wimg_hi[img][e] = hi;
    g_wimg_lo[img][e] = lo;
}

// ---------------------------------------------------------------------------
// Bucket fill
// ---------------------------------------------------------------------------
__global__ void bucket_fill(const int* __restrict__ pid, const int* __restrict__ hid,
                            const float* __restrict__ ew, int nE) {
    int e = blockIdx.x * 256 + threadIdx.x;
    if (e >= nE) return;
    int p = __ldg(pid + e);
    int h = __ldg(hid + e);
    float w = __ldg(ew + e);
    int s = atomicAdd(&g_cntH[h], 1);
    if (s < CAPH) g_bktH[h * CAPH + s] = make_int2(p, __float_as_int(w));
    else { int o = atomicAdd(&g_ovfH_cnt, 1); g_ovfH[o] = e; }
    s = atomicAdd(&g_cntP[p], 1);
    if (s < CAPP) g_bktP[p * CAPP + s] = make_int2(h, __float_as_int(w));
    else { int o = atomicAdd(&g_ovfP_cnt, 1); g_ovfP[o] = e; }
}

// ---------------------------------------------------------------------------
// Gather 1: he_feat[b] = sum over bucket of feat[pid] * w
// Bucket staged in smem; unroll-8 with 4 accumulators for MLP.
// ---------------------------------------------------------------------------
__global__ void __launch_bounds__(128)
gather_he(const float* __restrict__ feat) {
    __shared__ int2 sbk[CAPH];
    int b = blockIdx.x, tid = threadIdx.x;
    int n = g_cntH[b];
    if (n > CAPH) n = CAPH;
    for (int i = tid; i < n; i += 128) sbk[i] = __ldg(&g_bktH[b * CAPH + i]);
    __syncthreads();

    float a0 = 0.f, a1 = 0.f, a2 = 0.f, a3 = 0.f;
    int i = 0;
    for (; i + 8 <= n; i += 8) {
        float f[8], w[8];
#pragma unroll
        for (int j = 0; j < 8; j++) {
            int2 e = sbk[i + j];
            f[j] = __ldg(feat + (size_t)e.x * 128 + tid);
            w[j] = __int_as_float(e.y);
        }
        a0 += f[0] * w[0] + f[4] * w[4];
        a1 += f[1] * w[1] + f[5] * w[5];
        a2 += f[2] * w[2] + f[6] * w[6];
        a3 += f[3] * w[3] + f[7] * w[7];
    }
    for (; i < n; i++) {
        int2 e = sbk[i];
        a0 += __ldg(feat + (size_t)e.x * 128 + tid) * __int_as_float(e.y);
    }
    g_he_feat[b * 128 + tid] = (a0 + a1) + (a2 + a3);
}

__global__ void ovf_replay_he(const float* __restrict__ feat,
                              const float* __restrict__ ew,
                              const int* __restrict__ pid,
                              const int* __restrict__ hid) {
    int total = g_ovfH_cnt * 32;
    for (int t = blockIdx.x * blockDim.x + threadIdx.x; t < total;
         t += gridDim.x * blockDim.x) {
        int i = t >> 5, lane = t & 31;
        int e = g_ovfH[i];
        int p = __ldg(pid + e), h = __ldg(hid + e);
        float w = __ldg(ew + e);
        float4 v = __ldg((const float4*)feat + p * 32 + lane);
        float* dst = g_he_feat + h * 128 + lane * 4;
        asm volatile("red.global.add.v4.f32 [%0], {%1,%2,%3,%4};"
                     :: "l"(dst), "f"(v.x * w), "f"(v.y * w), "f"(v.z * w), "f"(v.w * w)
                     : "memory");
    }
}

// ---------------------------------------------------------------------------
// Attention GEMM: g_h = relu(he_feat @ Wh1 + bh1)  (imgs 8,9; y = col half)
// ---------------------------------------------------------------------------
__global__ void __launch_bounds__(256, 1)
attn_gemm(const float* __restrict__ bh1, int nHE) {
    extern __shared__ char smem[];
    int tid = threadIdx.x;
    int wid = tid >> 5, lane = tid & 31;
    int warpM = (wid & 3) * 32, warpN = (wid >> 2) * 64;
    int y = blockIdx.y;
    int row0 = blockIdx.x * 128;

    float acc[2][8][4];
#pragma unroll
    for (int m = 0; m < 2; m++)
#pragma unroll
        for (int n = 0; n < 8; n++)
#pragma unroll
            for (int i = 0; i < 4; i++) acc[m][n][i] = 0.f;

    stage_A_f32(g_he_feat, 128, row0, nHE, 0, smem + OFF_AHI, smem + OFF_ALO, tid);
    copy_B(g_wimg_hi[8 + y], g_wimg_lo[8 + y], smem + OFF_BHI, smem + OFF_BLO, tid);
    __syncthreads();
    hmma_chunk(smem, warpM, warpN, lane, acc);

    epi_f32(acc, bh1 + y * 128, g_h + y * 128, 256, row0, nHE, true,
            warpM, warpN, lane);
}

__global__ void __launch_bounds__(256)
attn_fuse(const float* __restrict__ Wh2, const float* __restrict__ bh2,
          const float* __restrict__ Wfuse, int nHE) {
    int wq = threadIdx.x >> 5, lane = threadIdx.x & 31;
    int he = blockIdx.x * 8 + wq;
    if (he >= nHE) return;
    const float* hr = g_h + (size_t)he * 256;
    float att = 0.f;
#pragma unroll
    for (int hh = 0; hh < 4; hh++) {
        float s = __ldg(hr + hh * 64 + lane) * __ldg(Wh2 + hh * 64 + lane)
                + __ldg(hr + hh * 64 + 32 + lane) * __ldg(Wh2 + hh * 64 + 32 + lane);
#pragma unroll
        for (int o = 16; o; o >>= 1) s += __shfl_xor_sync(0xffffffffu, s, o);
        float sg = 1.f / (1.f + expf(-(s + __ldg(bh2 + hh))));
        att += sg * __ldg(Wfuse + hh);
    }
    float4 f = __ldg((const float4*)(g_he_feat + (size_t)he * 128) + lane);
    f.x *= att; f.y *= att; f.z *= att; f.w *= att;
    *((float4*)(g_he_weighted + (size_t)he * 128) + lane) = f;
}

// ---------------------------------------------------------------------------
// Gather 2: cluster[p] = sum over bucket of he_weighted[hid] * w
// ---------------------------------------------------------------------------
__global__ void __launch_bounds__(128)
gather_p() {
    __shared__ int2 sbk[CAPP];
    int p = blockIdx.x, tid = threadIdx.x;
    int n = g_cntP[p];
    if (n > CAPP) n = CAPP;
    if (tid < n) sbk[tid] = __ldg(&g_bktP[p * CAPP + tid]);
    __syncthreads();

    float a0 = 0.f, a1 = 0.f, a2 = 0.f, a3 = 0.f;
    int i = 0;
    for (; i + 8 <= n; i += 8) {
        float f[8], w[8];
#pragma unroll
        for (int j = 0; j < 8; j++) {
            int2 e = sbk[i + j];
            f[j] = g_he_weighted[(size_t)e.x * 128 + tid];
            w[j] = __int_as_float(e.y);
        }
        a0 += f[0] * w[0] + f[4] * w[4];
        a1 += f[1] * w[1] + f[5] * w[5];
        a2 += f[2] * w[2] + f[6] * w[6];
        a3 += f[3] * w[3] + f[7] * w[7];
    }
    for (; i < n; i++) {
        int2 e = sbk[i];
        a0 += g_he_weighted[(size_t)e.x * 128 + tid] * __int_as_float(e.y);
    }
    g_cluster[p * 128 + tid] = (a0 + a1) + (a2 + a3);
}

__global__ void ovf_replay_p(const float* __restrict__ ew,
                             const int* __restrict__ pid,
                             const int* __restrict__ hid) {
    int total = g_ovfP_cnt * 32;
    for (int t = blockIdx.x * blockDim.x + threadIdx.x; t < total;
         t += gridDim.x * blockDim.x) {
        int i = t >> 5, lane = t & 31;
        int e = g_ovfP[i];
        int p = __ldg(pid + e), h = __ldg(hid + e);
        float w = __ldg(ew + e);
        float4 v = *(const float4*)(g_he_weighted + h * 128 + lane * 4);
        float* dst = g_cluster + p * 128 + lane * 4;
        asm volatile("red.global.add.v4.f32 [%0], {%1,%2,%3,%4};"
                     :: "l"(dst), "f"(v.x * w), "f"(v.y * w), "f"(v.z * w), "f"(v.w * w)
                     : "memory");
    }
}

// ---------------------------------------------------------------------------
// GEMM A: projections -> split-bf16 cat images (y=0 self half, y=1 clu half)
// ---------------------------------------------------------------------------
__global__ void __launch_bounds__(256, 1)
proj_tc(const float* __restrict__ feat,
        const float* __restrict__ bself, const float* __restrict__ bclu, int nP) {
    extern __shared__ char smem[];
    int tid = threadIdx.x;
    int wid = tid >> 5, lane = tid & 31;
    int warpM = (wid & 3) * 32, warpN = (wid >> 2) * 64;
    int y = blockIdx.y;
    int row0 = blockIdx.x * 128;
    const float* A = y ? g_cluster : feat;
    const float* bias = y ? bclu : bself;

    float acc[2][8][4];
#pragma unroll
    for (int m = 0; m < 2; m++)
#pragma unroll
        for (int n = 0; n < 8; n++)
#pragma unroll
            for (int i = 0; i < 4; i++) acc[m][n][i] = 0.f;

    stage_A_f32(A, 128, row0, nP, 0, smem + OFF_AHI, smem + OFF_ALO, tid);
    copy_B(g_wimg_hi[y], g_wimg_lo[y], smem + OFF_BHI, smem + OFF_BLO, tid);
    __syncthreads();
    hmma_chunk(smem, warpM, warpN, lane, acc);

    epi_bf16(acc, bias, g_cat_hi, g_cat_lo, y * 128, row0, nP, false,
             warpM, warpN, lane);
}

// ---------------------------------------------------------------------------
// GEMM B: t1 = relu(cat @ Wf1 + bf1) -> split-bf16 t1 images. y = col half.
// ---------------------------------------------------------------------------
__global__ void __launch_bounds__(256, 1)
mlp1_tc(const float* __restrict__ bf1, int nP) {
    extern __shared__ char smem[];
    int tid = threadIdx.x;
    int wid = tid >> 5, lane = tid & 31;
    int warpM = (wid & 3) * 32, warpN = (wid >> 2) * 64;
    int y = blockIdx.y;
    int row0 = blockIdx.x * 128;
    int colOff = y * 128;

    float acc[2][8][4];
#pragma unroll
    for (int m = 0; m < 2; m++)
#pragma unroll
        for (int n = 0; n < 8; n++)
#pragma unroll
            for (int i = 0; i < 4; i++) acc[m][n][i] = 0.f;

#pragma unroll
    for (int ch = 0; ch < 2; ch++) {
        if (ch) __syncthreads();
        stage_A_bf16(g_cat_hi, g_cat_lo, row0, ch * 128,
                     smem + OFF_AHI, smem + OFF_ALO, tid);
        copy_B(g_wimg_hi[2 + y * 2 + ch], g_wimg_lo[2 + y * 2 + ch],
               smem + OFF_BHI, smem + OFF_BLO, tid);
        __syncthreads();
        hmma_chunk(smem, warpM, warpN, lane, acc);
    }

    epi_bf16(acc, bf1 + colOff, g_t1_hi, g_t1_lo, colOff, row0, nP, true,
             warpM, warpN, lane);
}

// ---------------------------------------------------------------------------
// GEMM C: t2 = relu(t1 @ Wf2 + bf2); fw = softmax(t2@Wf3+bf3);
//         out = relu(self_f*fw0 + clu_f*fw1 + feat)
// ---------------------------------------------------------------------------
#define LDT2 129
__global__ void __launch_bounds__(256, 1)
mlp2_tc(const float* __restrict__ feat,
        const float* __restrict__ bf2,
        const float* __restrict__ Wf3, const float* __restrict__ bf3,
        float* __restrict__ out, int nP) {
    extern __shared__ char smem[];
    int tid = threadIdx.x;
    int wid = tid >> 5, lane = tid & 31;
    int warpM = (wid & 3) * 32, warpN = (wid >> 2) * 64;
    int row0 = blockIdx.x * 128;

    float acc[2][8][4];
#pragma unroll
    for (int m = 0; m < 2; m++)
#pragma unroll
        for (int n = 0; n < 8; n++)
#pragma unroll
            for (int i = 0; i < 4; i++) acc[m][n][i] = 0.f;

#pragma unroll
    for (int ch = 0; ch < 2; ch++) {
        if (ch) __syncthreads();
        stage_A_bf16(g_t1_hi, g_t1_lo, row0, ch * 128,
                     smem + OFF_AHI, smem + OFF_ALO, tid);
        copy_B(g_wimg_hi[6 + ch], g_wimg_lo[6 + ch],
               smem + OFF_BHI, smem + OFF_BLO, tid);
        __syncthreads();
        hmma_chunk(smem, warpM, warpN, lane, acc);
    }
    __syncthreads();

    float* sT2 = (float*)smem;
    float* sFW = (float*)(smem + 128 * LDT2 * 4);
    {
        int qr = lane >> 2, qc = lane & 3;
#pragma unroll
        for (int mt = 0; mt < 2; mt++) {
#pragma unroll
            for (int nt = 0; nt < 8; nt++) {
                int col = warpN + nt * 8 + qc * 2;
                float b0 = __ldg(bf2 + col), b1 = __ldg(bf2 + col + 1);
#pragma unroll
                for (int half = 0; half < 2; half++) {
                    int r = warpM + mt * 16 + qr + half * 8;
                    sT2[r * LDT2 + col] =
                        fmaxf(acc[mt][nt][half * 2 + 0] + b0, 0.f);
                    sT2[r * LDT2 + col + 1] =
                        fmaxf(acc[mt][nt][half * 2 + 1] + b1, 0.f);
                }
            }
        }
    }
    __syncthreads();

    if (tid < 128) {
        float l0 = __ldg(bf3), l1 = __ldg(bf3 + 1);
        const float* trow = sT2 + tid * LDT2;
#pragma unroll 8
        for (int k = 0; k < 128; k++) {
            float v = trow[k];
            l0 += v * __ldg(Wf3 + 2 * k);
            l1 += v * __ldg(Wf3 + 2 * k + 1);
        }
        float w0 = 1.f / (1.f + expf(l1 - l0));
        sFW[2 * tid] = w0;
        sFW[2 * tid + 1] = 1.f - w0;
    }
    __syncthreads();

    // final fuse: self/clu reconstructed as hi + lo
    for (int idx = tid; idx < 128 * 32; idx += 256) {
        int r = idx >> 5, c4 = idx & 31;
        int grow = row0 + r;
        if (grow < nP) {
            float w0 = sFW[2 * r], w1 = sFW[2 * r + 1];
            size_t so = (size_t)grow * 256 + c4 * 4;
            size_t co = so + 128;
            uint2 sh = *(const uint2*)(g_cat_hi + so);
            uint2 sl = *(const uint2*)(g_cat_lo + so);
            uint2 ch = *(const uint2*)(g_cat_hi + co);
            uint2 cl = *(const uint2*)(g_cat_lo + co);
            const __nv_bfloat16* shp = (const __nv_bfloat16*)&sh;
            const __nv_bfloat16* slp = (const __nv_bfloat16*)&sl;
            const __nv_bfloat16* chp = (const __nv_bfloat16*)&ch;
            const __nv_bfloat16* clp = (const __nv_bfloat16*)&cl;
            float4 f = __ldg((const float4*)(feat + (size_t)grow * 128) + c4);
            float4 o;
            float s0 = __bfloat162float(shp[0]) + __bfloat162float(slp[0]);
            float s1 = __bfloat162float(shp[1]) + __bfloat162float(slp[1]);
            float s2 = __bfloat162float(shp[2]) + __bfloat162float(slp[2]);
            float s3 = __bfloat162float(shp[3]) + __bfloat162float(slp[3]);
            float c0 = __bfloat162float(chp[0]) + __bfloat162float(clp[0]);
            float c1 = __bfloat162float(chp[1]) + __bfloat162float(clp[1]);
            float c2 = __bfloat162float(chp[2]) + __bfloat162float(clp[2]);
            float c3 = __bfloat162float(chp[3]) + __bfloat162float(clp[3]);
            o.x = fmaxf(s0 * w0 + c0 * w1 + f.x, 0.f);
            o.y = fmaxf(s1 * w0 + c1 * w1 + f.y, 0.f);
            o.z = fmaxf(s2 * w0 + c2 * w1 + f.z, 0.f);
            o.w = fmaxf(s3 * w0 + c3 * w1 + f.w, 0.f);
            *(float4*)(out + (size_t)grow * 128 + c4 * 4) = o;
        }
    }
}

// ---------------------------------------------------------------------------
extern "C" void kernel_launch(void* const* d_in, const int* in_sizes, int n_in,
                              void* d_out, int out_size) {
    const float* feat   = (const float*)d_in[0];
    const float* edge_w = (const float*)d_in[1];
    const float* Wself  = (const float*)d_in[2];
    const float* bself  = (const float*)d_in[3];
    const float* Wclu   = (const float*)d_in[4];
    const float* bclu   = (const float*)d_in[5];
    const float* Wh1    = (const float*)d_in[6];
    const float* bh1    = (const float*)d_in[7];
    const float* Wh2    = (const float*)d_in[8];
    const float* bh2    = (const float*)d_in[9];
    const float* Wfuse  = (const float*)d_in[10];
    const float* Wf1    = (const float*)d_in[11];
    const float* bf1    = (const float*)d_in[12];
    const float* Wf2    = (const float*)d_in[13];
    const float* bf2    = (const float*)d_in[14];
    const float* Wf3    = (const float*)d_in[15];
    const float* bf3    = (const float*)d_in[16];
    const int* edge_pid = (const int*)d_in[17];
    const int* edge_hid = (const int*)d_in[18];

    int nP  = in_sizes[0] / 128;
    int nE  = in_sizes[17];
    int nHE = NHE_MAX;

    zero_counts_kernel<<<(NP_MAX + 255) / 256, 256>>>();
    prep_weights<<<640, 256>>>(Wself, Wclu, Wf1, Wf2, Wh1);
    bucket_fill<<<(nE + 255) / 256, 256>>>(edge_pid, edge_hid, edge_w, nE);

    gather_he<<<nHE, 128>>>(feat);
    ovf_replay_he<<<64, 256>>>(feat, edge_w, edge_pid, edge_hid);

    int nBlkH = (nHE + 127) / 128;
    cudaFuncSetAttribute(attn_gemm, cudaFuncAttributeMaxDynamicSharedMemorySize,
                         TC_SMEM_BYTES);
    attn_gemm<<<dim3(nBlkH, 2), 256, TC_SMEM_BYTES>>>(bh1, nHE);
    attn_fuse<<<(nHE + 7) / 8, 256>>>(Wh2, bh2, Wfuse, nHE);

    gather_p<<<nP, 128>>>();
    ovf_replay_p<<<64, 256>>>(edge_w, edge_pid, edge_hid);

    int nBlk = (nP + 127) / 128;
    cudaFuncSetAttribute(proj_tc, cudaFuncAttributeMaxDynamicSharedMemorySize,
                         TC_SMEM_BYTES);
    proj_tc<<<dim3(nBlk, 2), 256, TC_SMEM_BYTES>>>(feat, bself, bclu, nP);

    cudaFuncSetAttribute(mlp1_tc, cudaFuncAttributeMaxDynamicSharedMemorySize,
                         TC_SMEM_BYTES);
    mlp1_tc<<<dim3(nBlk, 2), 256, TC_SMEM_BYTES>>>(bf1, nP);

    cudaFuncSetAttribute(mlp2_tc, cudaFuncAttributeMaxDynamicSharedMemorySize,
                         TC_SMEM_BYTES);
    mlp2_tc<<<nBlk, 256, TC_SMEM_BYTES>>>(feat, bf2, Wf3, bf3, (float*)d_out, nP);
}

// round 11
// speedup vs baseline: 1.0556x; 1.0556x over previous
#include <cuda_runtime.h>
#include <cuda_bf16.h>
#include <math.h>
#include <stdint.h>

#define NP_MAX 50000
#define NP_PAD 50048
#define NHE_MAX 5000
#define DIN 128
#define CAPH 256
#define CAPP 64

// ---------------------------------------------------------------------------
// Device scratch (no allocations allowed)
// ---------------------------------------------------------------------------
__device__ float g_he_feat[NHE_MAX * DIN];       // 2.56 MB
__device__ float g_he_weighted[NHE_MAX * DIN];   // 2.56 MB
__device__ float g_cluster[NP_MAX * DIN];        // 25.6 MB
__device__ float g_h[NHE_MAX * 256];             // 5.12 MB (attn hidden)

// Split-bf16 activation images (written by GEMM epilogues, read as MMA A)
__device__ __align__(16) __nv_bfloat16 g_cat_hi[NP_PAD * 256];   // 25.6 MB
__device__ __align__(16) __nv_bfloat16 g_cat_lo[NP_PAD * 256];
__device__ __align__(16) __nv_bfloat16 g_t1_hi[NP_PAD * 256];
__device__ __align__(16) __nv_bfloat16 g_t1_lo[NP_PAD * 256];

// Bucketed edge lists (gather form of the two segment-sums)
__device__ int2 g_bktH[NHE_MAX * CAPH];          // {pid, w}  10.2 MB
__device__ int2 g_bktP[NP_MAX * CAPP];           // {hid, w}  25.6 MB
__device__ int g_cntH[NHE_MAX];
__device__ int g_cntP[NP_MAX];
__device__ int g_ovfH_cnt, g_ovfP_cnt;
__device__ int g_ovfH[800000];
__device__ int g_ovfP[800000];

// bf16 weight images, [n][k] row-major:
// 0: Wself | 1: Wclu | 2,3: Wf1 col0 ch0/1 | 4,5: Wf1 col1 ch0/1 | 6,7: Wf2 | 8,9: Wh1
__device__ __align__(16) __nv_bfloat16 g_wimg_hi[10][128 * 128];
__device__ __align__(16) __nv_bfloat16 g_wimg_lo[10][128 * 128];

__device__ __forceinline__ unsigned int packbf2(__nv_bfloat16 a, __nv_bfloat16 b) {
    return ((unsigned int)__bfloat16_as_ushort(b) << 16) | __bfloat16_as_ushort(a);
}

// ---------------------------------------------------------------------------
// mma.sync m16n8k16 bf16 (baseline PTX, HMMA on sm_103)
// ---------------------------------------------------------------------------
__device__ __forceinline__ void mma_bf16(float* d, const unsigned* a, const unsigned* b) {
    asm volatile(
        "mma.sync.aligned.m16n8k16.row.col.f32.bf16.bf16.f32 "
        "{%0,%1,%2,%3}, {%4,%5,%6,%7}, {%8,%9}, {%0,%1,%2,%3};"
        : "+f"(d[0]), "+f"(d[1]), "+f"(d[2]), "+f"(d[3])
        : "r"(a[0]), "r"(a[1]), "r"(a[2]), "r"(a[3]), "r"(b[0]), "r"(b[1]));
}

// ---------------------------------------------------------------------------
// SMEM: K=64 chunks. A hi/lo + B hi/lo, each [128][72] bf16 (stride 144 B:
// 36 words/row -> frag bank = (4r+qc) mod 32, conflict-free).
// 73728 B/block -> 2 blocks/SM for cross-block stage/MMA overlap.
// ---------------------------------------------------------------------------
#define STRB 144
#define OFF_AHI 0
#define OFF_ALO (128 * STRB)
#define OFF_BHI (2 * 128 * STRB)
#define OFF_BLO (3 * 128 * STRB)
#define TC_SMEM_BYTES (4 * 128 * STRB)   // 73728

// Stage fp32 A chunk [128 x 64] -> bf16 hi/lo split into smem
__device__ __forceinline__ void stage_A_f32(const float* __restrict__ A, int ldA,
                                            int row0, int nRows, int k0,
                                            char* sAhi, char* sAlo, int tid) {
#pragma unroll
    for (int i = 0; i < 8; i++) {
        int g = tid + 256 * i;             // 2048 float4 = 128 rows x 16
        int r = g >> 4, c4 = g & 15;
        int grow = row0 + r;
        float4 v = {0.f, 0.f, 0.f, 0.f};
        if (grow < nRows)
            v = __ldg((const float4*)(A + (size_t)grow * ldA + k0) + c4);
        __nv_bfloat16 h0 = __float2bfloat16(v.x), h1 = __float2bfloat16(v.y);
        __nv_bfloat16 h2 = __float2bfloat16(v.z), h3 = __float2bfloat16(v.w);
        __nv_bfloat16 l0 = __float2bfloat16(v.x - __bfloat162float(h0));
        __nv_bfloat16 l1 = __float2bfloat16(v.y - __bfloat162float(h1));
        __nv_bfloat16 l2 = __float2bfloat16(v.z - __bfloat162float(h2));
        __nv_bfloat16 l3 = __float2bfloat16(v.w - __bfloat162float(h3));
        uint2 hu, lu;
        hu.x = packbf2(h0, h1); hu.y = packbf2(h2, h3);
        lu.x = packbf2(l0, l1); lu.y = packbf2(l2, l3);
        int off = r * STRB + c4 * 8;
        *(uint2*)(sAhi + off) = hu;
        *(uint2*)(sAlo + off) = lu;
    }
}

// Stage pre-split bf16 A chunk [128 x 64] (pure copy; global row = 256 bf16)
__device__ __forceinline__ void stage_A_bf16(const __nv_bfloat16* __restrict__ hi,
                                             const __nv_bfloat16* __restrict__ lo,
                                             int row0, int k0,
                                             char* sAhi, char* sAlo, int tid) {
#pragma unroll
    for (int i = 0; i < 4; i++) {
        int idx = tid + 256 * i;           // 1024 uint4 = 128 rows x 128 B
        int r = idx >> 3, kg = idx & 7;
        size_t gofs = (size_t)(row0 + r) * 256 + k0;
        uint4 h = __ldg((const uint4*)(hi + gofs) + kg);
        uint4 l = __ldg((const uint4*)(lo + gofs) + kg);
        *(uint4*)(sAhi + r * STRB + kg * 16) = h;
        *(uint4*)(sAlo + r * STRB + kg * 16) = l;
    }
}

// Copy weight image K-chunk [128 n x 64 k] (image row = 128 bf16)
__device__ __forceinline__ void copy_B(const __nv_bfloat16* hi, const __nv_bfloat16* lo,
                                       int k0, char* sBhi, char* sBlo, int tid) {
#pragma unroll
    for (int i = 0; i < 4; i++) {
        int idx = tid + 256 * i;
        int n = idx >> 3, kg = idx & 7;
        uint4 h = __ldg((const uint4*)(hi + n * 128 + k0) + kg);
        uint4 l = __ldg((const uint4*)(lo + n * 128 + k0) + kg);
        *(uint4*)(sBhi + n * STRB + kg * 16) = h;
        *(uint4*)(sBlo + n * STRB + kg * 16) = l;
    }
}

// One K=64 chunk of HMMA (4 k-steps x 3 split terms)
__device__ __forceinline__ void hmma_chunk(const char* sm, int warpM, int warpN,
                                           int lane, float acc[2][8][4]) {
    int qr = lane >> 2, qc = lane & 3;
    const char* sAhi = sm + OFF_AHI;
    const char* sAlo = sm + OFF_ALO;
    const char* sBhi = sm + OFF_BHI;
    const char* sBlo = sm + OFF_BLO;
#pragma unroll
    for (int ks = 0; ks < 4; ks++) {
        int k0 = ks * 16;
        unsigned ah[2][4], al[2][4];
#pragma unroll
        for (int mt = 0; mt < 2; mt++) {
            int r = warpM + mt * 16 + qr;
            int cb = (k0 + qc * 2) * 2;
            const char* p0 = sAhi + r * STRB + cb;
            const char* p1 = sAhi + (r + 8) * STRB + cb;
            ah[mt][0] = *(const unsigned*)p0;
            ah[mt][1] = *(const unsigned*)p1;
            ah[mt][2] = *(const unsigned*)(p0 + 16);
            ah[mt][3] = *(const unsigned*)(p1 + 16);
            const char* q0 = sAlo + r * STRB + cb;
            const char* q1 = sAlo + (r + 8) * STRB + cb;
            al[mt][0] = *(const unsigned*)q0;
            al[mt][1] = *(const unsigned*)q1;
            al[mt][2] = *(const unsigned*)(q0 + 16);
            al[mt][3] = *(const unsigned*)(q1 + 16);
        }
#pragma unroll
        for (int nt = 0; nt < 8; nt++) {
            int n = warpN + nt * 8 + qr;
            int cb = (k0 + qc * 2) * 2;
            unsigned bh[2], bl[2];
            const char* pb = sBhi + n * STRB + cb;
            bh[0] = *(const unsigned*)pb;
            bh[1] = *(const unsigned*)(pb + 16);
            const char* pl = sBlo + n * STRB + cb;
            bl[0] = *(const unsigned*)pl;
            bl[1] = *(const unsigned*)(pl + 16);
#pragma unroll
            for (int mt = 0; mt < 2; mt++) {
                mma_bf16(acc[mt][nt], ah[mt], bh);
                mma_bf16(acc[mt][nt], ah[mt], bl);
                mma_bf16(acc[mt][nt], al[mt], bh);
            }
        }
    }
}

// Epilogue to fp32 global (attn path)
__device__ __forceinline__ void epi_f32(const float acc[2][8][4],
                                        const float* __restrict__ bias,
                                        float* __restrict__ outBase, int ldOut,
                                        int row0, int nRows, bool relu,
                                        int warpM, int warpN, int lane) {
    int qr = lane >> 2, qc = lane & 3;
#pragma unroll
    for (int mt = 0; mt < 2; mt++) {
#pragma unroll
        for (int nt = 0; nt < 8; nt++) {
            int col = warpN + nt * 8 + qc * 2;
            float b0 = __ldg(bias + col), b1 = __ldg(bias + col + 1);
            int r0 = row0 + warpM + mt * 16 + qr;
#pragma unroll
            for (int half = 0; half < 2; half++) {
                int grow = r0 + half * 8;
                if (grow < nRows) {
                    float2 v;
                    v.x = acc[mt][nt][half * 2 + 0] + b0;
                    v.y = acc[mt][nt][half * 2 + 1] + b1;
                    if (relu) { v.x = fmaxf(v.x, 0.f); v.y = fmaxf(v.y, 0.f); }
                    *(float2*)(outBase + (size_t)grow * ldOut + col) = v;
                }
            }
        }
    }
}

// Epilogue to split-bf16 images (rows of 256, write at colOff + warp cols)
__device__ __forceinline__ void epi_bf16(const float acc[2][8][4],
                                         const float* __restrict__ bias,
                                         __nv_bfloat16* __restrict__ hiImg,
                                         __nv_bfloat16* __restrict__ loImg,
                                         int colOff, int row0, int nRows, bool relu,
                                         int warpM, int warpN, int lane) {
    int qr = lane >> 2, qc = lane & 3;
#pragma unroll
    for (int mt = 0; mt < 2; mt++) {
#pragma unroll
        for (int nt = 0; nt < 8; nt++) {
            int col = warpN + nt * 8 + qc * 2;
            float b0 = __ldg(bias + col), b1 = __ldg(bias + col + 1);
            int gcol = colOff + col;
            int r0 = row0 + warpM + mt * 16 + qr;
#pragma unroll
            for (int half = 0; half < 2; half++) {
                int grow = r0 + half * 8;
                if (grow < nRows) {
                    float vx = acc[mt][nt][half * 2 + 0] + b0;
                    float vy = acc[mt][nt][half * 2 + 1] + b1;
                    if (relu) { vx = fmaxf(vx, 0.f); vy = fmaxf(vy, 0.f); }
                    __nv_bfloat16 hx = __float2bfloat16(vx);
                    __nv_bfloat16 hy = __float2bfloat16(vy);
                    __nv_bfloat16 lx = __float2bfloat16(vx - __bfloat162float(hx));
                    __nv_bfloat16 ly = __float2bfloat16(vy - __bfloat162float(hy));
                    size_t o = (size_t)grow * 256 + gcol;
                    *(unsigned*)(hiImg + o) = packbf2(hx, hy);
                    *(unsigned*)(loImg + o) = packbf2(lx, ly);
                }
            }
        }
    }
}

// ---------------------------------------------------------------------------
// Setup kernels
// ---------------------------------------------------------------------------
__global__ void zero_counts_kernel() {
    int i = blockIdx.x * blockDim.x + threadIdx.x;
    if (i < NP_MAX) g_cntP[i] = 0;
    if (i < NHE_MAX) g_cntH[i] = 0;
    if (i == 0) { g_ovfH_cnt = 0; g_ovfP_cnt = 0; }
}

__global__ void prep_weights(const float* __restrict__ Wself,
                             const float* __restrict__ Wclu,
                             const float* __restrict__ Wf1,
                             const float* __restrict__ Wf2,
                             const float* __restrict__ Wh1) {
    int g = blockIdx.x * 256 + threadIdx.x;   // 163840 total
    int img = g >> 14;
    int e = g & 16383;
    int n = e >> 7, k = e & 127;
    float val;
    switch (img) {
        case 0: val = __ldg(Wself + k * 128 + n); break;
        case 1: val = __ldg(Wclu + k * 128 + n); break;
        case 2: val = __ldg(Wf1 + k * 256 + n); break;
        case 3: val = __ldg(Wf1 + (128 + k) * 256 + n); break;
        case 4: val = __ldg(Wf1 + k * 256 + 128 + n); break;
        case 5: val = __ldg(Wf1 + (128 + k) * 256 + 128 + n); break;
        case 6: val = __ldg(Wf2 + k * 128 + n); break;
        case 7: val = __ldg(Wf2 + (128 + k) * 128 + n); break;
        case 8: val = __ldg(Wh1 + ((n >> 6) * 128 + k) * 64 + (n & 63)); break;
        default: val = __ldg(Wh1 + ((2 + (n >> 6)) * 128 + k) * 64 + (n & 63)); break;
    }
    __nv_bfloat16 hi = __float2bfloat16(val);
    __nv_bfloat16 lo = __float2bfloat16(val - __bfloat162float(hi));
    g_wimg_hi[img][e] = hi;
    g_wimg_lo[img][e] = lo;
}

// ---------------------------------------------------------------------------
// Bucket fill
// ---------------------------------------------------------------------------
__global__ void bucket_fill(const int* __restrict__ pid, const int* __restrict__ hid,
                            const float* __restrict__ ew, int nE) {
    int e = blockIdx.x * 256 + threadIdx.x;
    if (e >= nE) return;
    int p = __ldg(pid + e);
    int h = __ldg(hid + e);
    float w = __ldg(ew + e);
    int s = atomicAdd(&g_cntH[h], 1);
    if (s < CAPH) g_bktH[h * CAPH + s] = make_int2(p, __float_as_int(w));
    else { int o = atomicAdd(&g_ovfH_cnt, 1); g_ovfH[o] = e; }
    s = atomicAdd(&g_cntP[p], 1);
    if (s < CAPP) g_bktP[p * CAPP + s] = make_int2(h, __float_as_int(w));
    else { int o = atomicAdd(&g_ovfP_cnt, 1); g_ovfP[o] = e; }
}

// ---------------------------------------------------------------------------
// Gather 1: he_feat[b] = sum over bucket of feat[pid] * w
// ---------------------------------------------------------------------------
__global__ void __launch_bounds__(128)
gather_he(const float* __restrict__ feat) {
    __shared__ int2 sbk[CAPH];
    int b = blockIdx.x, tid = threadIdx.x;
    int n = g_cntH[b];
    if (n > CAPH) n = CAPH;
    for (int i = tid; i < n; i += 128) sbk[i] = __ldg(&g_bktH[b * CAPH + i]);
    __syncthreads();

    float a0 = 0.f, a1 = 0.f, a2 = 0.f, a3 = 0.f;
    int i = 0;
    for (; i + 8 <= n; i += 8) {
        float f[8], w[8];
#pragma unroll
        for (int j = 0; j < 8; j++) {
            int2 e = sbk[i + j];
            f[j] = __ldg(feat + (size_t)e.x * 128 + tid);
            w[j] = __int_as_float(e.y);
        }
        a0 += f[0] * w[0] + f[4] * w[4];
        a1 += f[1] * w[1] + f[5] * w[5];
        a2 += f[2] * w[2] + f[6] * w[6];
        a3 += f[3] * w[3] + f[7] * w[7];
    }
    for (; i < n; i++) {
        int2 e = sbk[i];
        a0 += __ldg(feat + (size_t)e.x * 128 + tid) * __int_as_float(e.y);
    }
    g_he_feat[b * 128 + tid] = (a0 + a1) + (a2 + a3);
}

__global__ void ovf_replay_he(const float* __restrict__ feat,
                              const float* __restrict__ ew,
                              const int* __restrict__ pid,
                              const int* __restrict__ hid) {
    int total = g_ovfH_cnt * 32;
    for (int t = blockIdx.x * blockDim.x + threadIdx.x; t < total;
         t += gridDim.x * blockDim.x) {
        int i = t >> 5, lane = t & 31;
        int e = g_ovfH[i];
        int p = __ldg(pid + e), h = __ldg(hid + e);
        float w = __ldg(ew + e);
        float4 v = __ldg((const float4*)feat + p * 32 + lane);
        float* dst = g_he_feat + h * 128 + lane * 4;
        asm volatile("red.global.add.v4.f32 [%0], {%1,%2,%3,%4};"
                     :: "l"(dst), "f"(v.x * w), "f"(v.y * w), "f"(v.z * w), "f"(v.w * w)
                     : "memory");
    }
}

// ---------------------------------------------------------------------------
// Attention GEMM: g_h = relu(he_feat @ Wh1 + bh1)  (imgs 8,9; y = col half)
// ---------------------------------------------------------------------------
__global__ void __launch_bounds__(256, 2)
attn_gemm(const float* __restrict__ bh1, int nHE) {
    extern __shared__ char smem[];
    int tid = threadIdx.x;
    int wid = tid >> 5, lane = tid & 31;
    int warpM = (wid & 3) * 32, warpN = (wid >> 2) * 64;
    int y = blockIdx.y;
    int row0 = blockIdx.x * 128;

    float acc[2][8][4];
#pragma unroll
    for (int m = 0; m < 2; m++)
#pragma unroll
        for (int n = 0; n < 8; n++)
#pragma unroll
            for (int i = 0; i < 4; i++) acc[m][n][i] = 0.f;

#pragma unroll
    for (int ch = 0; ch < 2; ch++) {
        if (ch) __syncthreads();
        stage_A_f32(g_he_feat, 128, row0, nHE, ch * 64,
                    smem + OFF_AHI, smem + OFF_ALO, tid);
        copy_B(g_wimg_hi[8 + y], g_wimg_lo[8 + y], ch * 64,
               smem + OFF_BHI, smem + OFF_BLO, tid);
        __syncthreads();
        hmma_chunk(smem, warpM, warpN, lane, acc);
    }

    epi_f32(acc, bh1 + y * 128, g_h + y * 128, 256, row0, nHE, true,
            warpM, warpN, lane);
}

__global__ void __launch_bounds__(256)
attn_fuse(const float* __restrict__ Wh2, const float* __restrict__ bh2,
          const float* __restrict__ Wfuse, int nHE) {
    int wq = threadIdx.x >> 5, lane = threadIdx.x & 31;
    int he = blockIdx.x * 8 + wq;
    if (he >= nHE) return;
    const float* hr = g_h + (size_t)he * 256;
    float att = 0.f;
#pragma unroll
    for (int hh = 0; hh < 4; hh++) {
        float s = __ldg(hr + hh * 64 + lane) * __ldg(Wh2 + hh * 64 + lane)
                + __ldg(hr + hh * 64 + 32 + lane) * __ldg(Wh2 + hh * 64 + 32 + lane);
#pragma unroll
        for (int o = 16; o; o >>= 1) s += __shfl_xor_sync(0xffffffffu, s, o);
        float sg = 1.f / (1.f + expf(-(s + __ldg(bh2 + hh))));
        att += sg * __ldg(Wfuse + hh);
    }
    float4 f = __ldg((const float4*)(g_he_feat + (size_t)he * 128) + lane);
    f.x *= att; f.y *= att; f.z *= att; f.w *= att;
    *((float4*)(g_he_weighted + (size_t)he * 128) + lane) = f;
}

// ---------------------------------------------------------------------------
// Gather 2: cluster[p] = sum over bucket of he_weighted[hid] * w
// ---------------------------------------------------------------------------
__global__ void __launch_bounds__(128)
gather_p() {
    __shared__ int2 sbk[CAPP];
    int p = blockIdx.x, tid = threadIdx.x;
    int n = g_cntP[p];
    if (n > CAPP) n = CAPP;
    if (tid < n) sbk[tid] = __ldg(&g_bktP[p * CAPP + tid]);
    __syncthreads();

    float a0 = 0.f, a1 = 0.f, a2 = 0.f, a3 = 0.f;
    int i = 0;
    for (; i + 8 <= n; i += 8) {
        float f[8], w[8];
#pragma unroll
        for (int j = 0; j < 8; j++) {
            int2 e = sbk[i + j];
            f[j] = g_he_weighted[(size_t)e.x * 128 + tid];
            w[j] = __int_as_float(e.y);
        }
        a0 += f[0] * w[0] + f[4] * w[4];
        a1 += f[1] * w[1] + f[5] * w[5];
        a2 += f[2] * w[2] + f[6] * w[6];
        a3 += f[3] * w[3] + f[7] * w[7];
    }
    for (; i < n; i++) {
        int2 e = sbk[i];
        a0 += g_he_weighted[(size_t)e.x * 128 + tid] * __int_as_float(e.y);
    }
    g_cluster[p * 128 + tid] = (a0 + a1) + (a2 + a3);
}

__global__ void ovf_replay_p(const float* __restrict__ ew,
                             const int* __restrict__ pid,
                             const int* __restrict__ hid) {
    int total = g_ovfP_cnt * 32;
    for (int t = blockIdx.x * blockDim.x + threadIdx.x; t < total;
         t += gridDim.x * blockDim.x) {
        int i = t >> 5, lane = t & 31;
        int e = g_ovfP[i];
        int p = __ldg(pid + e), h = __ldg(hid + e);
        float w = __ldg(ew + e);
        float4 v = *(const float4*)(g_he_weighted + h * 128 + lane * 4);
        float* dst = g_cluster + p * 128 + lane * 4;
        asm volatile("red.global.add.v4.f32 [%0], {%1,%2,%3,%4};"
                     :: "l"(dst), "f"(v.x * w), "f"(v.y * w), "f"(v.z * w), "f"(v.w * w)
                     : "memory");
    }
}

// ---------------------------------------------------------------------------
// GEMM A: projections -> split-bf16 cat images (y=0 self half, y=1 clu half)
// ---------------------------------------------------------------------------
__global__ void __launch_bounds__(256, 2)
proj_tc(const float* __restrict__ feat,
        const float* __restrict__ bself, const float* __restrict__ bclu, int nP) {
    extern __shared__ char smem[];
    int tid = threadIdx.x;
    int wid = tid >> 5, lane = tid & 31;
    int warpM = (wid & 3) * 32, warpN = (wid >> 2) * 64;
    int y = blockIdx.y;
    int row0 = blockIdx.x * 128;
    const float* A = y ? g_cluster : feat;
    const float* bias = y ? bclu : bself;

    float acc[2][8][4];
#pragma unroll
    for (int m = 0; m < 2; m++)
#pragma unroll
        for (int n = 0; n < 8; n++)
#pragma unroll
            for (int i = 0; i < 4; i++) acc[m][n][i] = 0.f;

#pragma unroll
    for (int ch = 0; ch < 2; ch++) {
        if (ch) __syncthreads();
        stage_A_f32(A, 128, row0, nP, ch * 64, smem + OFF_AHI, smem + OFF_ALO, tid);
        copy_B(g_wimg_hi[y], g_wimg_lo[y], ch * 64,
               smem + OFF_BHI, smem + OFF_BLO, tid);
        __syncthreads();
        hmma_chunk(smem, warpM, warpN, lane, acc);
    }

    epi_bf16(acc, bias, g_cat_hi, g_cat_lo, y * 128, row0, nP, false,
             warpM, warpN, lane);
}

// ---------------------------------------------------------------------------
// GEMM B: t1 = relu(cat @ Wf1 + bf1) -> split-bf16 t1 images. y = col half.
// ---------------------------------------------------------------------------
__global__ void __launch_bounds__(256, 2)
mlp1_tc(const float* __restrict__ bf1, int nP) {
    extern __shared__ char smem[];
    int tid = threadIdx.x;
    int wid = tid >> 5, lane = tid & 31;
    int warpM = (wid & 3) * 32, warpN = (wid >> 2) * 64;
    int y = blockIdx.y;
    int row0 = blockIdx.x * 128;
    int colOff = y * 128;

    float acc[2][8][4];
#pragma unroll
    for (int m = 0; m < 2; m++)
#pragma unroll
        for (int n = 0; n < 8; n++)
#pragma unroll
            for (int i = 0; i < 4; i++) acc[m][n][i] = 0.f;

#pragma unroll
    for (int ch = 0; ch < 4; ch++) {
        if (ch) __syncthreads();
        stage_A_bf16(g_cat_hi, g_cat_lo, row0, ch * 64,
                     smem + OFF_AHI, smem + OFF_ALO, tid);
        int img = 2 + y * 2 + (ch >> 1);
        copy_B(g_wimg_hi[img], g_wimg_lo[img], (ch & 1) * 64,
               smem + OFF_BHI, smem + OFF_BLO, tid);
        __syncthreads();
        hmma_chunk(smem, warpM, warpN, lane, acc);
    }

    epi_bf16(acc, bf1 + colOff, g_t1_hi, g_t1_lo, colOff, row0, nP, true,
             warpM, warpN, lane);
}

// ---------------------------------------------------------------------------
// GEMM C: t2 = relu(t1 @ Wf2 + bf2); fw = softmax(t2@Wf3+bf3);
//         out = relu(self_f*fw0 + clu_f*fw1 + feat)
// ---------------------------------------------------------------------------
#define LDT2 129
__global__ void __launch_bounds__(256, 2)
mlp2_tc(const float* __restrict__ feat,
        const float* __restrict__ bf2,
        const float* __restrict__ Wf3, const float* __restrict__ bf3,
        float* __restrict__ out, int nP) {
    extern __shared__ char smem[];
    int tid = threadIdx.x;
    int wid = tid >> 5, lane = tid & 31;
    int warpM = (wid & 3) * 32, warpN = (wid >> 2) * 64;
    int row0 = blockIdx.x * 128;

    float acc[2][8][4];
#pragma unroll
    for (int m = 0; m < 2; m++)
#pragma unroll
        for (int n = 0; n < 8; n++)
#pragma unroll
            for (int i = 0; i < 4; i++) acc[m][n][i] = 0.f;

#pragma unroll
    for (int ch = 0; ch < 4; ch++) {
        if (ch) __syncthreads();
        stage_A_bf16(g_t1_hi, g_t1_lo, row0, ch * 64,
                     smem + OFF_AHI, smem + OFF_ALO, tid);
        int img = 6 + (ch >> 1);
        copy_B(g_wimg_hi[img], g_wimg_lo[img], (ch & 1) * 64,
               smem + OFF_BHI, smem + OFF_BLO, tid);
        __syncthreads();
        hmma_chunk(smem, warpM, warpN, lane, acc);
    }
    __syncthreads();

    float* sT2 = (float*)smem;                     // 128*129*4 = 66048 <= 73728
    float* sFW = (float*)(smem + 128 * LDT2 * 4);
    {
        int qr = lane >> 2, qc = lane & 3;
#pragma unroll
        for (int mt = 0; mt < 2; mt++) {
#pragma unroll
            for (int nt = 0; nt < 8; nt++) {
                int col = warpN + nt * 8 + qc * 2;
                float b0 = __ldg(bf2 + col), b1 = __ldg(bf2 + col + 1);
#pragma unroll
                for (int half = 0; half < 2; half++) {
                    int r = warpM + mt * 16 + qr + half * 8;
                    sT2[r * LDT2 + col] =
                        fmaxf(acc[mt][nt][half * 2 + 0] + b0, 0.f);
                    sT2[r * LDT2 + col + 1] =
                        fmaxf(acc[mt][nt][half * 2 + 1] + b1, 0.f);
                }
            }
        }
    }
    __syncthreads();

    if (tid < 128) {
        float l0 = __ldg(bf3), l1 = __ldg(bf3 + 1);
        const float* trow = sT2 + tid * LDT2;
#pragma unroll 8
        for (int k = 0; k < 128; k++) {
            float v = trow[k];
            l0 += v * __ldg(Wf3 + 2 * k);
            l1 += v * __ldg(Wf3 + 2 * k + 1);
        }
        float w0 = 1.f / (1.f + expf(l1 - l0));
        sFW[2 * tid] = w0;
        sFW[2 * tid + 1] = 1.f - w0;
    }
    __syncthreads();

    // final fuse: self/clu reconstructed as hi + lo
    for (int idx = tid; idx < 128 * 32; idx += 256) {
        int r = idx >> 5, c4 = idx & 31;
        int grow = row0 + r;
        if (grow < nP) {
            float w0 = sFW[2 * r], w1 = sFW[2 * r + 1];
            size_t so = (size_t)grow * 256 + c4 * 4;
            size_t co = so + 128;
            uint2 sh = *(const uint2*)(g_cat_hi + so);
            uint2 sl = *(const uint2*)(g_cat_lo + so);
            uint2 ch = *(const uint2*)(g_cat_hi + co);
            uint2 cl = *(const uint2*)(g_cat_lo + co);
            const __nv_bfloat16* shp = (const __nv_bfloat16*)&sh;
            const __nv_bfloat16* slp = (const __nv_bfloat16*)&sl;
            const __nv_bfloat16* chp = (const __nv_bfloat16*)&ch;
            const __nv_bfloat16* clp = (const __nv_bfloat16*)&cl;
            float4 f = __ldg((const float4*)(feat + (size_t)grow * 128) + c4);
            float4 o;
            float s0 = __bfloat162float(shp[0]) + __bfloat162float(slp[0]);
            float s1 = __bfloat162float(shp[1]) + __bfloat162float(slp[1]);
            float s2 = __bfloat162float(shp[2]) + __bfloat162float(slp[2]);
            float s3 = __bfloat162float(shp[3]) + __bfloat162float(slp[3]);
            float c0 = __bfloat162float(chp[0]) + __bfloat162float(clp[0]);
            float c1 = __bfloat162float(chp[1]) + __bfloat162float(clp[1]);
            float c2 = __bfloat162float(chp[2]) + __bfloat162float(clp[2]);
            float c3 = __bfloat162float(chp[3]) + __bfloat162float(clp[3]);
            o.x = fmaxf(s0 * w0 + c0 * w1 + f.x, 0.f);
            o.y = fmaxf(s1 * w0 + c1 * w1 + f.y, 0.f);
            o.z = fmaxf(s2 * w0 + c2 * w1 + f.z, 0.f);
            o.w = fmaxf(s3 * w0 + c3 * w1 + f.w, 0.f);
            *(float4*)(out + (size_t)grow * 128 + c4 * 4) = o;
        }
    }
}

// ---------------------------------------------------------------------------
extern "C" void kernel_launch(void* const* d_in, const int* in_sizes, int n_in,
                              void* d_out, int out_size) {
    const float* feat   = (const float*)d_in[0];
    const float* edge_w = (const float*)d_in[1];
    const float* Wself  = (const float*)d_in[2];
    const float* bself  = (const float*)d_in[3];
    const float* Wclu   = (const float*)d_in[4];
    const float* bclu   = (const float*)d_in[5];
    const float* Wh1    = (const float*)d_in[6];
    const float* bh1    = (const float*)d_in[7];
    const float* Wh2    = (const float*)d_in[8];
    const float* bh2    = (const float*)d_in[9];
    const float* Wfuse  = (const float*)d_in[10];
    const float* Wf1    = (const float*)d_in[11];
    const float* bf1    = (const float*)d_in[12];
    const float* Wf2    = (const float*)d_in[13];
    const float* bf2    = (const float*)d_in[14];
    const float* Wf3    = (const float*)d_in[15];
    const float* bf3    = (const float*)d_in[16];
    const int* edge_pid = (const int*)d_in[17];
    const int* edge_hid = (const int*)d_in[18];

    int nP  = in_sizes[0] / 128;
    int nE  = in_sizes[17];
    int nHE = NHE_MAX;

    zero_counts_kernel<<<(NP_MAX + 255) / 256, 256>>>();
    prep_weights<<<640, 256>>>(Wself, Wclu, Wf1, Wf2, Wh1);
    bucket_fill<<<(nE + 255) / 256, 256>>>(edge_pid, edge_hid, edge_w, nE);

    gather_he<<<nHE, 128>>>(feat);
    ovf_replay_he<<<64, 256>>>(feat, edge_w, edge_pid, edge_hid);

    int nBlkH = (nHE + 127) / 128;
    cudaFuncSetAttribute(attn_gemm, cudaFuncAttributeMaxDynamicSharedMemorySize,
                         TC_SMEM_BYTES);
    attn_gemm<<<dim3(nBlkH, 2), 256, TC_SMEM_BYTES>>>(bh1, nHE);
    attn_fuse<<<(nHE + 7) / 8, 256>>>(Wh2, bh2, Wfuse, nHE);

    gather_p<<<nP, 128>>>();
    ovf_replay_p<<<64, 256>>>(edge_w, edge_pid, edge_hid);

    int nBlk = (nP + 127) / 128;
    cudaFuncSetAttribute(proj_tc, cudaFuncAttributeMaxDynamicSharedMemorySize,
                         TC_SMEM_BYTES);
    proj_tc<<<dim3(nBlk, 2), 256, TC_SMEM_BYTES>>>(feat, bself, bclu, nP);

    cudaFuncSetAttribute(mlp1_tc, cudaFuncAttributeMaxDynamicSharedMemorySize,
                         TC_SMEM_BYTES);
    mlp1_tc<<<dim3(nBlk, 2), 256, TC_SMEM_BYTES>>>(bf1, nP);

    cudaFuncSetAttribute(mlp2_tc, cudaFuncAttributeMaxDynamicSharedMemorySize,
                         TC_SMEM_BYTES);
    mlp2_tc<<<nBlk, 256, TC_SMEM_BYTES>>>(feat, bf2, Wf3, bf3, (float*)d_out, nP);
}

// round 12
// speedup vs baseline: 1.0798x; 1.0229x over previous
#include <cuda_runtime.h>
#include <cuda_bf16.h>
#include <math.h>
#include <stdint.h>

#define NP_MAX 50000
#define NP_PAD 50048
#define NHE_MAX 5000
#define DIN 128
#define CAPH 256
#define CAPP 64

// ---------------------------------------------------------------------------
// Device scratch (no allocations allowed)
// ---------------------------------------------------------------------------
__device__ float g_he_feat[NHE_MAX * DIN];       // 2.56 MB
__device__ float g_he_weighted[NHE_MAX * DIN];   // 2.56 MB
__device__ float g_cluster[NP_MAX * DIN];        // 25.6 MB
__device__ float g_h[NHE_MAX * 256];             // 5.12 MB (attn hidden)

// Split-bf16 activation images (written by GEMM epilogues, read as MMA A)
__device__ __align__(16) __nv_bfloat16 g_cat_hi[NP_PAD * 256];   // 25.6 MB
__device__ __align__(16) __nv_bfloat16 g_cat_lo[NP_PAD * 256];
__device__ __align__(16) __nv_bfloat16 g_t1_hi[NP_PAD * 256];
__device__ __align__(16) __nv_bfloat16 g_t1_lo[NP_PAD * 256];

// Bucketed edge lists (gather form of the two segment-sums)
__device__ int2 g_bktH[NHE_MAX * CAPH];          // {pid, w}  10.2 MB
__device__ int2 g_bktP[NP_MAX * CAPP];           // {hid, w}  25.6 MB
__device__ int g_cntH[NHE_MAX];
__device__ int g_cntP[NP_MAX];
__device__ int g_ovfH_cnt, g_ovfP_cnt;
__device__ int g_ovfH[800000];
__device__ int g_ovfP[800000];

// bf16 weight images, [n][k] row-major:
// 0: Wself | 1: Wclu | 2,3: Wf1 col0 ch0/1 | 4,5: Wf1 col1 ch0/1 | 6,7: Wf2 | 8,9: Wh1
__device__ __align__(16) __nv_bfloat16 g_wimg_hi[10][128 * 128];
__device__ __align__(16) __nv_bfloat16 g_wimg_lo[10][128 * 128];

__device__ __forceinline__ unsigned int packbf2(__nv_bfloat16 a, __nv_bfloat16 b) {
    return ((unsigned int)__bfloat16_as_ushort(b) << 16) | __bfloat16_as_ushort(a);
}

// ---------------------------------------------------------------------------
// mma.sync m16n8k16 bf16 + ldmatrix (baseline PTX, HMMA/LDSM on sm_103)
// ---------------------------------------------------------------------------
__device__ __forceinline__ void mma_bf16(float* d, const unsigned* a, const unsigned* b) {
    asm volatile(
        "mma.sync.aligned.m16n8k16.row.col.f32.bf16.bf16.f32 "
        "{%0,%1,%2,%3}, {%4,%5,%6,%7}, {%8,%9}, {%0,%1,%2,%3};"
        : "+f"(d[0]), "+f"(d[1]), "+f"(d[2]), "+f"(d[3])
        : "r"(a[0]), "r"(a[1]), "r"(a[2]), "r"(a[3]), "r"(b[0]), "r"(b[1]));
}

__device__ __forceinline__ void ldsm_x4(unsigned* r, uint32_t addr) {
    asm volatile("ldmatrix.sync.aligned.m8n8.x4.shared.b16 {%0,%1,%2,%3}, [%4];"
                 : "=r"(r[0]), "=r"(r[1]), "=r"(r[2]), "=r"(r[3]) : "r"(addr));
}

// ---------------------------------------------------------------------------
// SMEM: K=64 chunks. A hi/lo + B hi/lo, each [128][72] bf16 (stride 144 B:
// 8 consecutive rows x 16B cover all 32 banks -> ldmatrix conflict-free).
// 73728 B/block -> 2 blocks/SM.
// ---------------------------------------------------------------------------
#define STRB 144
#define OFF_AHI 0
#define OFF_ALO (128 * STRB)
#define OFF_BHI (2 * 128 * STRB)
#define OFF_BLO (3 * 128 * STRB)
#define TC_SMEM_BYTES (4 * 128 * STRB)   // 73728

// Stage fp32 A chunk [128 x 64] -> bf16 hi/lo split into smem
__device__ __forceinline__ void stage_A_f32(const float* __restrict__ A, int ldA,
                                            int row0, int nRows, int k0,
                                            char* sAhi, char* sAlo, int tid) {
#pragma unroll
    for (int i = 0; i < 8; i++) {
        int g = tid + 256 * i;             // 2048 float4 = 128 rows x 16
        int r = g >> 4, c4 = g & 15;
        int grow = row0 + r;
        float4 v = {0.f, 0.f, 0.f, 0.f};
        if (grow < nRows)
            v = __ldg((const float4*)(A + (size_t)grow * ldA + k0) + c4);
        __nv_bfloat16 h0 = __float2bfloat16(v.x), h1 = __float2bfloat16(v.y);
        __nv_bfloat16 h2 = __float2bfloat16(v.z), h3 = __float2bfloat16(v.w);
        __nv_bfloat16 l0 = __float2bfloat16(v.x - __bfloat162float(h0));
        __nv_bfloat16 l1 = __float2bfloat16(v.y - __bfloat162float(h1));
        __nv_bfloat16 l2 = __float2bfloat16(v.z - __bfloat162float(h2));
        __nv_bfloat16 l3 = __float2bfloat16(v.w - __bfloat162float(h3));
        uint2 hu, lu;
        hu.x = packbf2(h0, h1); hu.y = packbf2(h2, h3);
        lu.x = packbf2(l0, l1); lu.y = packbf2(l2, l3);
        int off = r * STRB + c4 * 8;
        *(uint2*)(sAhi + off) = hu;
        *(uint2*)(sAlo + off) = lu;
    }
}

// Stage pre-split bf16 A chunk [128 x 64] (pure copy; global row = 256 bf16)
__device__ __forceinline__ void stage_A_bf16(const __nv_bfloat16* __restrict__ hi,
                                             const __nv_bfloat16* __restrict__ lo,
                                             int row0, int k0,
                                             char* sAhi, char* sAlo, int tid) {
#pragma unroll
    for (int i = 0; i < 4; i++) {
        int idx = tid + 256 * i;           // 1024 uint4 = 128 rows x 128 B
        int r = idx >> 3, kg = idx & 7;
        size_t gofs = (size_t)(row0 + r) * 256 + k0;
        uint4 h = __ldg((const uint4*)(hi + gofs) + kg);
        uint4 l = __ldg((const uint4*)(lo + gofs) + kg);
        *(uint4*)(sAhi + r * STRB + kg * 16) = h;
        *(uint4*)(sAlo + r * STRB + kg * 16) = l;
    }
}

// Copy weight image K-chunk [128 n x 64 k] (image row = 128 bf16)
__device__ __forceinline__ void copy_B(const __nv_bfloat16* hi, const __nv_bfloat16* lo,
                                       int k0, char* sBhi, char* sBlo, int tid) {
#pragma unroll
    for (int i = 0; i < 4; i++) {
        int idx = tid + 256 * i;
        int n = idx >> 3, kg = idx & 7;
        uint4 h = __ldg((const uint4*)(hi + n * 128 + k0) + kg);
        uint4 l = __ldg((const uint4*)(lo + n * 128 + k0) + kg);
        *(uint4*)(sBhi + n * STRB + kg * 16) = h;
        *(uint4*)(sBlo + n * STRB + kg * 16) = l;
    }
}

// One K=64 chunk of HMMA (4 k-steps x 3 split terms), ldmatrix fragments
__device__ __forceinline__ void hmma_chunk(const char* sm, int warpM, int warpN,
                                           int lane, float acc[2][8][4]) {
    uint32_t aBase = (uint32_t)__cvta_generic_to_shared(sm + OFF_AHI);
    uint32_t bBase = (uint32_t)__cvta_generic_to_shared(sm + OFF_BHI);
    // A x4: lanes 0-7 rows+0 k0 | 8-15 rows+8 k0 | 16-23 rows+0 k+16B | 24-31 rows+8 k+16B
    int aRow = warpM + ((lane >> 3) & 1) * 8 + (lane & 7);
    uint32_t aAddr = aBase + aRow * STRB + ((lane >> 4) & 1) * 16;
    // B x4: lanes 0-7 n+0 k0 | 8-15 n+0 k+16B | 16-23 n+8 k0 | 24-31 n+8 k+16B
    int bRow = warpN + ((lane >> 4) & 1) * 8 + (lane & 7);
    uint32_t bAddr = bBase + bRow * STRB + ((lane >> 3) & 1) * 16;
    const uint32_t LOFF = 128 * STRB;   // hi -> lo image offset

#pragma unroll
    for (int ks = 0; ks < 4; ks++) {
        unsigned ah[2][4], al[2][4];
        ldsm_x4(ah[0], aAddr);
        ldsm_x4(ah[1], aAddr + 16 * STRB);
        ldsm_x4(al[0], aAddr + LOFF);
        ldsm_x4(al[1], aAddr + LOFF + 16 * STRB);
#pragma unroll
        for (int ntp = 0; ntp < 4; ntp++) {
            unsigned bh[4], bl[4];   // {nt even b0,b1, nt odd b0,b1}
            ldsm_x4(bh, bAddr + ntp * (16 * STRB));
            ldsm_x4(bl, bAddr + ntp * (16 * STRB) + LOFF);
#pragma unroll
            for (int sub = 0; sub < 2; sub++) {
                int nt = ntp * 2 + sub;
                const unsigned* bhp = bh + sub * 2;
                const unsigned* blp = bl + sub * 2;
#pragma unroll
                for (int mt = 0; mt < 2; mt++) {
                    mma_bf16(acc[mt][nt], ah[mt], bhp);
                    mma_bf16(acc[mt][nt], ah[mt], blp);
                    mma_bf16(acc[mt][nt], al[mt], bhp);
                }
            }
        }
        aAddr += 32;
        bAddr += 32;
    }
}

// Epilogue to fp32 global (attn path)
__device__ __forceinline__ void epi_f32(const float acc[2][8][4],
                                        const float* __restrict__ bias,
                                        float* __restrict__ outBase, int ldOut,
                                        int row0, int nRows, bool relu,
                                        int warpM, int warpN, int lane) {
    int qr = lane >> 2, qc = lane & 3;
#pragma unroll
    for (int mt = 0; mt < 2; mt++) {
#pragma unroll
        for (int nt = 0; nt < 8; nt++) {
            int col = warpN + nt * 8 + qc * 2;
            float b0 = __ldg(bias + col), b1 = __ldg(bias + col + 1);
            int r0 = row0 + warpM + mt * 16 + qr;
#pragma unroll
            for (int half = 0; half < 2; half++) {
                int grow = r0 + half * 8;
                if (grow < nRows) {
                    float2 v;
                    v.x = acc[mt][nt][half * 2 + 0] + b0;
                    v.y = acc[mt][nt][half * 2 + 1] + b1;
                    if (relu) { v.x = fmaxf(v.x, 0.f); v.y = fmaxf(v.y, 0.f); }
                    *(float2*)(outBase + (size_t)grow * ldOut + col) = v;
                }
            }
        }
    }
}

// Epilogue to split-bf16 images (rows of 256, write at colOff + warp cols)
__device__ __forceinline__ void epi_bf16(const float acc[2][8][4],
                                         const float* __restrict__ bias,
                                         __nv_bfloat16* __restrict__ hiImg,
                                         __nv_bfloat16* __restrict__ loImg,
                                         int colOff, int row0, int nRows, bool relu,
                                         int warpM, int warpN, int lane) {
    int qr = lane >> 2, qc = lane & 3;
#pragma unroll
    for (int mt = 0; mt < 2; mt++) {
#pragma unroll
        for (int nt = 0; nt < 8; nt++) {
            int col = warpN + nt * 8 + qc * 2;
            float b0 = __ldg(bias + col), b1 = __ldg(bias + col + 1);
            int gcol = colOff + col;
            int r0 = row0 + warpM + mt * 16 + qr;
#pragma unroll
            for (int half = 0; half < 2; half++) {
                int grow = r0 + half * 8;
                if (grow < nRows) {
                    float vx = acc[mt][nt][half * 2 + 0] + b0;
                    float vy = acc[mt][nt][half * 2 + 1] + b1;
                    if (relu) { vx = fmaxf(vx, 0.f); vy = fmaxf(vy, 0.f); }
                    __nv_bfloat16 hx = __float2bfloat16(vx);
                    __nv_bfloat16 hy = __float2bfloat16(vy);
                    __nv_bfloat16 lx = __float2bfloat16(vx - __bfloat162float(hx));
                    __nv_bfloat16 ly = __float2bfloat16(vy - __bfloat162float(hy));
                    size_t o = (size_t)grow * 256 + gcol;
                    *(unsigned*)(hiImg + o) = packbf2(hx, hy);
                    *(unsigned*)(loImg + o) = packbf2(lx, ly);
                }
            }
        }
    }
}

// ---------------------------------------------------------------------------
// Setup kernels
// ---------------------------------------------------------------------------
__global__ void zero_counts_kernel() {
    int i = blockIdx.x * blockDim.x + threadIdx.x;
    if (i < NP_MAX) g_cntP[i] = 0;
    if (i < NHE_MAX) g_cntH[i] = 0;
    if (i == 0) { g_ovfH_cnt = 0; g_ovfP_cnt = 0; }
}

__global__ void prep_weights(const float* __restrict__ Wself,
                             const float* __restrict__ Wclu,
                             const float* __restrict__ Wf1,
                             const float* __restrict__ Wf2,
                             const float* __restrict__ Wh1) {
    int g = blockIdx.x * 256 + threadIdx.x;   // 163840 total
    int img = g >> 14;
    int e = g & 16383;
    int n = e >> 7, k = e & 127;
    float val;
    switch (img) {
        case 0: val = __ldg(Wself + k * 128 + n); break;
        case 1: val = __ldg(Wclu + k * 128 + n); break;
        case 2: val = __ldg(Wf1 + k * 256 + n); break;
        case 3: val = __ldg(Wf1 + (128 + k) * 256 + n); break;
        case 4: val = __ldg(Wf1 + k * 256 + 128 + n); break;
        case 5: val = __ldg(Wf1 + (128 + k) * 256 + 128 + n); break;
        case 6: val = __ldg(Wf2 + k * 128 + n); break;
        case 7: val = __ldg(Wf2 + (128 + k) * 128 + n); break;
        case 8: val = __ldg(Wh1 + ((n >> 6) * 128 + k) * 64 + (n & 63)); break;
        default: val = __ldg(Wh1 + ((2 + (n >> 6)) * 128 + k) * 64 + (n & 63)); break;
    }
    __nv_bfloat16 hi = __float2bfloat16(val);
    __nv_bfloat16 lo = __float2bfloat16(val - __bfloat162float(hi));
    g_wimg_hi[img][e] = hi;
    g_wimg_lo[img][e] = lo;
}

// ---------------------------------------------------------------------------
// Bucket fill
// ---------------------------------------------------------------------------
__global__ void bucket_fill(const int* __restrict__ pid, const int* __restrict__ hid,
                            const float* __restrict__ ew, int nE) {
    int e = blockIdx.x * 256 + threadIdx.x;
    if (e >= nE) return;
    int p = __ldg(pid + e);
    int h = __ldg(hid + e);
    float w = __ldg(ew + e);
    int s = atomicAdd(&g_cntH[h], 1);
    if (s < CAPH) g_bktH[h * CAPH + s] = make_int2(p, __float_as_int(w));
    else { int o = atomicAdd(&g_ovfH_cnt, 1); g_ovfH[o] = e; }
    s = atomicAdd(&g_cntP[p], 1);
    if (s < CAPP) g_bktP[p * CAPP + s] = make_int2(h, __float_as_int(w));
    else { int o = atomicAdd(&g_ovfP_cnt, 1); g_ovfP[o] = e; }
}

// ---------------------------------------------------------------------------
// Gather 1: he_feat[b] = sum over bucket of feat[pid] * w
// ---------------------------------------------------------------------------
__global__ void __launch_bounds__(128)
gather_he(const float* __restrict__ feat) {
    __shared__ int2 sbk[CAPH];
    int b = blockIdx.x, tid = threadIdx.x;
    int n = g_cntH[b];
    if (n > CAPH) n = CAPH;
    for (int i = tid; i < n; i += 128) sbk[i] = __ldg(&g_bktH[b * CAPH + i]);
    __syncthreads();

    float a0 = 0.f, a1 = 0.f, a2 = 0.f, a3 = 0.f;
    int i = 0;
    for (; i + 8 <= n; i += 8) {
        float f[8], w[8];
#pragma unroll
        for (int j = 0; j < 8; j++) {
            int2 e = sbk[i + j];
            f[j] = __ldg(feat + (size_t)e.x * 128 + tid);
            w[j] = __int_as_float(e.y);
        }
        a0 += f[0] * w[0] + f[4] * w[4];
        a1 += f[1] * w[1] + f[5] * w[5];
        a2 += f[2] * w[2] + f[6] * w[6];
        a3 += f[3] * w[3] + f[7] * w[7];
    }
    for (; i < n; i++) {
        int2 e = sbk[i];
        a0 += __ldg(feat + (size_t)e.x * 128 + tid) * __int_as_float(e.y);
    }
    g_he_feat[b * 128 + tid] = (a0 + a1) + (a2 + a3);
}

__global__ void ovf_replay_he(const float* __restrict__ feat,
                              const float* __restrict__ ew,
                              const int* __restrict__ pid,
                              const int* __restrict__ hid) {
    int total = g_ovfH_cnt * 32;
    for (int t = blockIdx.x * blockDim.x + threadIdx.x; t < total;
         t += gridDim.x * blockDim.x) {
        int i = t >> 5, lane = t & 31;
        int e = g_ovfH[i];
        int p = __ldg(pid + e), h = __ldg(hid + e);
        float w = __ldg(ew + e);
        float4 v = __ldg((const float4*)feat + p * 32 + lane);
        float* dst = g_he_feat + h * 128 + lane * 4;
        asm volatile("red.global.add.v4.f32 [%0], {%1,%2,%3,%4};"
                     :: "l"(dst), "f"(v.x * w), "f"(v.y * w), "f"(v.z * w), "f"(v.w * w)
                     : "memory");
    }
}

// ---------------------------------------------------------------------------
// Attention GEMM: g_h = relu(he_feat @ Wh1 + bh1)  (imgs 8,9; y = col half)
// ---------------------------------------------------------------------------
__global__ void __launch_bounds__(256, 2)
attn_gemm(const float* __restrict__ bh1, int nHE) {
    extern __shared__ char smem[];
    int tid = threadIdx.x;
    int wid = tid >> 5, lane = tid & 31;
    int warpM = (wid & 3) * 32, warpN = (wid >> 2) * 64;
    int y = blockIdx.y;
    int row0 = blockIdx.x * 128;

    float acc[2][8][4];
#pragma unroll
    for (int m = 0; m < 2; m++)
#pragma unroll
        for (int n = 0; n < 8; n++)
#pragma unroll
            for (int i = 0; i < 4; i++) acc[m][n][i] = 0.f;

#pragma unroll
    for (int ch = 0; ch < 2; ch++) {
        if (ch) __syncthreads();
        stage_A_f32(g_he_feat, 128, row0, nHE, ch * 64,
                    smem + OFF_AHI, smem + OFF_ALO, tid);
        copy_B(g_wimg_hi[8 + y], g_wimg_lo[8 + y], ch * 64,
               smem + OFF_BHI, smem + OFF_BLO, tid);
        __syncthreads();
        hmma_chunk(smem, warpM, warpN, lane, acc);
    }

    epi_f32(acc, bh1 + y * 128, g_h + y * 128, 256, row0, nHE, true,
            warpM, warpN, lane);
}

__global__ void __launch_bounds__(256)
attn_fuse(const float* __restrict__ Wh2, const float* __restrict__ bh2,
          const float* __restrict__ Wfuse, int nHE) {
    int wq = threadIdx.x >> 5, lane = threadIdx.x & 31;
    int he = blockIdx.x * 8 + wq;
    if (he >= nHE) return;
    const float* hr = g_h + (size_t)he * 256;
    float att = 0.f;
#pragma unroll
    for (int hh = 0; hh < 4; hh++) {
        float s = __ldg(hr + hh * 64 + lane) * __ldg(Wh2 + hh * 64 + lane)
                + __ldg(hr + hh * 64 + 32 + lane) * __ldg(Wh2 + hh * 64 + 32 + lane);
#pragma unroll
        for (int o = 16; o; o >>= 1) s += __shfl_xor_sync(0xffffffffu, s, o);
        float sg = 1.f / (1.f + expf(-(s + __ldg(bh2 + hh))));
        att += sg * __ldg(Wfuse + hh);
    }
    float4 f = __ldg((const float4*)(g_he_feat + (size_t)he * 128) + lane);
    f.x *= att; f.y *= att; f.z *= att; f.w *= att;
    *((float4*)(g_he_weighted + (size_t)he * 128) + lane) = f;
}

// ---------------------------------------------------------------------------
// Gather 2: cluster[p] = sum over bucket of he_weighted[hid] * w
// ---------------------------------------------------------------------------
__global__ void __launch_bounds__(128)
gather_p() {
    __shared__ int2 sbk[CAPP];
    int p = blockIdx.x, tid = threadIdx.x;
    int n = g_cntP[p];
    if (n > CAPP) n = CAPP;
    if (tid < n) sbk[tid] = __ldg(&g_bktP[p * CAPP + tid]);
    __syncthreads();

    float a0 = 0.f, a1 = 0.f, a2 = 0.f, a3 = 0.f;
    int i = 0;
    for (; i + 8 <= n; i += 8) {
        float f[8], w[8];
#pragma unroll
        for (int j = 0; j < 8; j++) {
            int2 e = sbk[i + j];
            f[j] = g_he_weighted[(size_t)e.x * 128 + tid];
            w[j] = __int_as_float(e.y);
        }
        a0 += f[0] * w[0] + f[4] * w[4];
        a1 += f[1] * w[1] + f[5] * w[5];
        a2 += f[2] * w[2] + f[6] * w[6];
        a3 += f[3] * w[3] + f[7] * w[7];
    }
    for (; i < n; i++) {
        int2 e = sbk[i];
        a0 += g_he_weighted[(size_t)e.x * 128 + tid] * __int_as_float(e.y);
    }
    g_cluster[p * 128 + tid] = (a0 + a1) + (a2 + a3);
}

__global__ void ovf_replay_p(const float* __restrict__ ew,
                             const int* __restrict__ pid,
                             const int* __restrict__ hid) {
    int total = g_ovfP_cnt * 32;
    for (int t = blockIdx.x * blockDim.x + threadIdx.x; t < total;
         t += gridDim.x * blockDim.x) {
        int i = t >> 5, lane = t & 31;
        int e = g_ovfP[i];
        int p = __ldg(pid + e), h = __ldg(hid + e);
        float w = __ldg(ew + e);
        float4 v = *(const float4*)(g_he_weighted + h * 128 + lane * 4);
        float* dst = g_cluster + p * 128 + lane * 4;
        asm volatile("red.global.add.v4.f32 [%0], {%1,%2,%3,%4};"
                     :: "l"(dst), "f"(v.x * w), "f"(v.y * w), "f"(v.z * w), "f"(v.w * w)
                     : "memory");
    }
}

// ---------------------------------------------------------------------------
// GEMM A: projections -> split-bf16 cat images (y=0 self half, y=1 clu half)
// ---------------------------------------------------------------------------
__global__ void __launch_bounds__(256, 2)
proj_tc(const float* __restrict__ feat,
        const float* __restrict__ bself, const float* __restrict__ bclu, int nP) {
    extern __shared__ char smem[];
    int tid = threadIdx.x;
    int wid = tid >> 5, lane = tid & 31;
    int warpM = (wid & 3) * 32, warpN = (wid >> 2) * 64;
    int y = blockIdx.y;
    int row0 = blockIdx.x * 128;
    const float* A = y ? g_cluster : feat;
    const float* bias = y ? bclu : bself;

    float acc[2][8][4];
#pragma unroll
    for (int m = 0; m < 2; m++)
#pragma unroll
        for (int n = 0; n < 8; n++)
#pragma unroll
            for (int i = 0; i < 4; i++) acc[m][n][i] = 0.f;

#pragma unroll
    for (int ch = 0; ch < 2; ch++) {
        if (ch) __syncthreads();
        stage_A_f32(A, 128, row0, nP, ch * 64, smem + OFF_AHI, smem + OFF_ALO, tid);
        copy_B(g_wimg_hi[y], g_wimg_lo[y], ch * 64,
               smem + OFF_BHI, smem + OFF_BLO, tid);
        __syncthreads();
        hmma_chunk(smem, warpM, warpN, lane, acc);
    }

    epi_bf16(acc, bias, g_cat_hi, g_cat_lo, y * 128, row0, nP, false,
             warpM, warpN, lane);
}

// ---------------------------------------------------------------------------
// GEMM B: t1 = relu(cat @ Wf1 + bf1) -> split-bf16 t1 images. y = col half.
// ---------------------------------------------------------------------------
__global__ void __launch_bounds__(256, 2)
mlp1_tc(const float* __restrict__ bf1, int nP) {
    extern __shared__ char smem[];
    int tid = threadIdx.x;
    int wid = tid >> 5, lane = tid & 31;
    int warpM = (wid & 3) * 32, warpN = (wid >> 2) * 64;
    int y = blockIdx.y;
    int row0 = blockIdx.x * 128;
    int colOff = y * 128;

    float acc[2][8][4];
#pragma unroll
    for (int m = 0; m < 2; m++)
#pragma unroll
        for (int n = 0; n < 8; n++)
#pragma unroll
            for (int i = 0; i < 4; i++) acc[m][n][i] = 0.f;

#pragma unroll
    for (int ch = 0; ch < 4; ch++) {
        if (ch) __syncthreads();
        stage_A_bf16(g_cat_hi, g_cat_lo, row0, ch * 64,
                     smem + OFF_AHI, smem + OFF_ALO, tid);
        int img = 2 + y * 2 + (ch >> 1);
        copy_B(g_wimg_hi[img], g_wimg_lo[img], (ch & 1) * 64,
               smem + OFF_BHI, smem + OFF_BLO, tid);
        __syncthreads();
        hmma_chunk(smem, warpM, warpN, lane, acc);
    }

    epi_bf16(acc, bf1 + colOff, g_t1_hi, g_t1_lo, colOff, row0, nP, true,
             warpM, warpN, lane);
}

// ---------------------------------------------------------------------------
// GEMM C: t2 = relu(t1 @ Wf2 + bf2); fw = softmax(t2@Wf3+bf3);
//         out = relu(self_f*fw0 + clu_f*fw1 + feat)
// ---------------------------------------------------------------------------
#define LDT2 129
__global__ void __launch_bounds__(256, 2)
mlp2_tc(const float* __restrict__ feat,
        const float* __restrict__ bf2,
        const float* __restrict__ Wf3, const float* __restrict__ bf3,
        float* __restrict__ out, int nP) {
    extern __shared__ char smem[];
    int tid = threadIdx.x;
    int wid = tid >> 5, lane = tid & 31;
    int warpM = (wid & 3) * 32, warpN = (wid >> 2) * 64;
    int row0 = blockIdx.x * 128;

    float acc[2][8][4];
#pragma unroll
    for (int m = 0; m < 2; m++)
#pragma unroll
        for (int n = 0; n < 8; n++)
#pragma unroll
            for (int i = 0; i < 4; i++) acc[m][n][i] = 0.f;

#pragma unroll
    for (int ch = 0; ch < 4; ch++) {
        if (ch) __syncthreads();
        stage_A_bf16(g_t1_hi, g_t1_lo, row0, ch * 64,
                     smem + OFF_AHI, smem + OFF_ALO, tid);
        int img = 6 + (ch >> 1);
        copy_B(g_wimg_hi[img], g_wimg_lo[img], (ch & 1) * 64,
               smem + OFF_BHI, smem + OFF_BLO, tid);
        __syncthreads();
        hmma_chunk(smem, warpM, warpN, lane, acc);
    }
    __syncthreads();

    float* sT2 = (float*)smem;                     // 128*129*4 = 66048 <= 73728
    float* sFW = (float*)(smem + 128 * LDT2 * 4);
    {
        int qr = lane >> 2, qc = lane & 3;
#pragma unroll
        for (int mt = 0; mt < 2; mt++) {
#pragma unroll
            for (int nt = 0; nt < 8; nt++) {
                int col = warpN + nt * 8 + qc * 2;
                float b0 = __ldg(bf2 + col), b1 = __ldg(bf2 + col + 1);
#pragma unroll
                for (int half = 0; half < 2; half++) {
                    int r = warpM + mt * 16 + qr + half * 8;
                    sT2[r * LDT2 + col] =
                        fmaxf(acc[mt][nt][half * 2 + 0] + b0, 0.f);
                    sT2[r * LDT2 + col + 1] =
                        fmaxf(acc[mt][nt][half * 2 + 1] + b1, 0.f);
                }
            }
        }
    }
    __syncthreads();

    if (tid < 128) {
        float l0 = __ldg(bf3), l1 = __ldg(bf3 + 1);
        const float* trow = sT2 + tid * LDT2;
#pragma unroll 8
        for (int k = 0; k < 128; k++) {
            float v = trow[k];
            l0 += v * __ldg(Wf3 + 2 * k);
            l1 += v * __ldg(Wf3 + 2 * k + 1);
        }
        float w0 = 1.f / (1.f + expf(l1 - l0));
        sFW[2 * tid] = w0;
        sFW[2 * tid + 1] = 1.f - w0;
    }
    __syncthreads();

    // final fuse: self/clu reconstructed as hi + lo
    for (int idx = tid; idx < 128 * 32; idx += 256) {
        int r = idx >> 5, c4 = idx & 31;
        int grow = row0 + r;
        if (grow < nP) {
            float w0 = sFW[2 * r], w1 = sFW[2 * r + 1];
            size_t so = (size_t)grow * 256 + c4 * 4;
            size_t co = so + 128;
            uint2 sh = *(const uint2*)(g_cat_hi + so);
            uint2 sl = *(const uint2*)(g_cat_lo + so);
            uint2 ch = *(const uint2*)(g_cat_hi + co);
            uint2 cl = *(const uint2*)(g_cat_lo + co);
            const __nv_bfloat16* shp = (const __nv_bfloat16*)&sh;
            const __nv_bfloat16* slp = (const __nv_bfloat16*)&sl;
            const __nv_bfloat16* chp = (const __nv_bfloat16*)&ch;
            const __nv_bfloat16* clp = (const __nv_bfloat16*)&cl;
            float4 f = __ldg((const float4*)(feat + (size_t)grow * 128) + c4);
            float4 o;
            float s0 = __bfloat162float(shp[0]) + __bfloat162float(slp[0]);
            float s1 = __bfloat162float(shp[1]) + __bfloat162float(slp[1]);
            float s2 = __bfloat162float(shp[2]) + __bfloat162float(slp[2]);
            float s3 = __bfloat162float(shp[3]) + __bfloat162float(slp[3]);
            float c0 = __bfloat162float(chp[0]) + __bfloat162float(clp[0]);
            float c1 = __bfloat162float(chp[1]) + __bfloat162float(clp[1]);
            float c2 = __bfloat162float(chp[2]) + __bfloat162float(clp[2]);
            float c3 = __bfloat162float(chp[3]) + __bfloat162float(clp[3]);
            o.x = fmaxf(s0 * w0 + c0 * w1 + f.x, 0.f);
            o.y = fmaxf(s1 * w0 + c1 * w1 + f.y, 0.f);
            o.z = fmaxf(s2 * w0 + c2 * w1 + f.z, 0.f);
            o.w = fmaxf(s3 * w0 + c3 * w1 + f.w, 0.f);
            *(float4*)(out + (size_t)grow * 128 + c4 * 4) = o;
        }
    }
}

// ---------------------------------------------------------------------------
extern "C" void kernel_launch(void* const* d_in, const int* in_sizes, int n_in,
                              void* d_out, int out_size) {
    const float* feat   = (const float*)d_in[0];
    const float* edge_w = (const float*)d_in[1];
    const float* Wself  = (const float*)d_in[2];
    const float* bself  = (const float*)d_in[3];
    const float* Wclu   = (const float*)d_in[4];
    const float* bclu   = (const float*)d_in[5];
    const float* Wh1    = (const float*)d_in[6];
    const float* bh1    = (const float*)d_in[7];
    const float* Wh2    = (const float*)d_in[8];
    const float* bh2    = (const float*)d_in[9];
    const float* Wfuse  = (const float*)d_in[10];
    const float* Wf1    = (const float*)d_in[11];
    const float* bf1    = (const float*)d_in[12];
    const float* Wf2    = (const float*)d_in[13];
    const float* bf2    = (const float*)d_in[14];
    const float* Wf3    = (const float*)d_in[15];
    const float* bf3    = (const float*)d_in[16];
    const int* edge_pid = (const int*)d_in[17];
    const int* edge_hid = (const int*)d_in[18];

    int nP  = in_sizes[0] / 128;
    int nE  = in_sizes[17];
    int nHE = NHE_MAX;

    zero_counts_kernel<<<(NP_MAX + 255) / 256, 256>>>();
    prep_weights<<<640, 256>>>(Wself, Wclu, Wf1, Wf2, Wh1);
    bucket_fill<<<(nE + 255) / 256, 256>>>(edge_pid, edge_hid, edge_w, nE);

    gather_he<<<nHE, 128>>>(feat);
    ovf_replay_he<<<64, 256>>>(feat, edge_w, edge_pid, edge_hid);

    int nBlkH = (nHE + 127) / 128;
    cudaFuncSetAttribute(attn_gemm, cudaFuncAttributeMaxDynamicSharedMemorySize,
                         TC_SMEM_BYTES);
    attn_gemm<<<dim3(nBlkH, 2), 256, TC_SMEM_BYTES>>>(bh1, nHE);
    attn_fuse<<<(nHE + 7) / 8, 256>>>(Wh2, bh2, Wfuse, nHE);

    gather_p<<<nP, 128>>>();
    ovf_replay_p<<<64, 256>>>(edge_w, edge_pid, edge_hid);

    int nBlk = (nP + 127) / 128;
    cudaFuncSetAttribute(proj_tc, cudaFuncAttributeMaxDynamicSharedMemorySize,
                         TC_SMEM_BYTES);
    proj_tc<<<dim3(nBlk, 2), 256, TC_SMEM_BYTES>>>(feat, bself, bclu, nP);

    cudaFuncSetAttribute(mlp1_tc, cudaFuncAttributeMaxDynamicSharedMemorySize,
                         TC_SMEM_BYTES);
    mlp1_tc<<<dim3(nBlk, 2), 256, TC_SMEM_BYTES>>>(bf1, nP);

    cudaFuncSetAttribute(mlp2_tc, cudaFuncAttributeMaxDynamicSharedMemorySize,
                         TC_SMEM_BYTES);
    mlp2_tc<<<nBlk, 256, TC_SMEM_BYTES>>>(feat, bf2, Wf3, bf3, (float*)d_out, nP);
}

// round 15
// speedup vs baseline: 1.0867x; 1.0064x over previous
#include <cuda_runtime.h>
#include <cuda_bf16.h>
#include <math.h>
#include <stdint.h>

#define NP_MAX 50000
#define NP_PAD 50048
#define NHE_MAX 5000
#define DIN 128
#define CAPH 256
#define CAPP 64

// ---------------------------------------------------------------------------
// Device scratch (no allocations allowed)
// ---------------------------------------------------------------------------
__device__ float g_he_feat[NHE_MAX * DIN];       // 2.56 MB
__device__ float g_he_weighted[NHE_MAX * DIN];   // 2.56 MB
__device__ float g_cluster[NP_MAX * DIN];        // 25.6 MB
__device__ float g_h[NHE_MAX * 256];             // 5.12 MB (attn hidden)

// Split-bf16 activation images (written by GEMM epilogues, read as MMA A)
__device__ __align__(16) __nv_bfloat16 g_cat_hi[NP_PAD * 256];   // 25.6 MB
__device__ __align__(16) __nv_bfloat16 g_cat_lo[NP_PAD * 256];
__device__ __align__(16) __nv_bfloat16 g_t1_hi[NP_PAD * 256];
__device__ __align__(16) __nv_bfloat16 g_t1_lo[NP_PAD * 256];

// Bucketed edge lists (gather form of the two segment-sums)
__device__ int2 g_bktH[NHE_MAX * CAPH];          // {pid, w}  10.2 MB
__device__ int2 g_bktP[NP_MAX * CAPP];           // {hid, w}  25.6 MB
__device__ int g_cntH[NHE_MAX];
__device__ int g_cntP[NP_MAX];
__device__ int g_ovfH_cnt, g_ovfP_cnt;
__device__ int g_ovfH[800000];
__device__ int g_ovfP[800000];

// bf16 weight images, [n][k] row-major:
// 0: Wself | 1: Wclu | 2,3: Wf1 col0 ch0/1 | 4,5: Wf1 col1 ch0/1 | 6,7: Wf2 | 8,9: Wh1
__device__ __align__(16) __nv_bfloat16 g_wimg_hi[10][128 * 128];
__device__ __align__(16) __nv_bfloat16 g_wimg_lo[10][128 * 128];

__device__ __forceinline__ unsigned int packbf2(__nv_bfloat16 a, __nv_bfloat16 b) {
    return ((unsigned int)__bfloat16_as_ushort(b) << 16) | __bfloat16_as_ushort(a);
}

// ---------------------------------------------------------------------------
// mma.sync m16n8k16 bf16 + ldmatrix (baseline PTX, HMMA/LDSM on sm_103)
// ---------------------------------------------------------------------------
__device__ __forceinline__ void mma_bf16(float* d, const unsigned* a, const unsigned* b) {
    asm volatile(
        "mma.sync.aligned.m16n8k16.row.col.f32.bf16.bf16.f32 "
        "{%0,%1,%2,%3}, {%4,%5,%6,%7}, {%8,%9}, {%0,%1,%2,%3};"
        : "+f"(d[0]), "+f"(d[1]), "+f"(d[2]), "+f"(d[3])
        : "r"(a[0]), "r"(a[1]), "r"(a[2]), "r"(a[3]), "r"(b[0]), "r"(b[1]));
}

__device__ __forceinline__ void ldsm_x4(unsigned* r, uint32_t addr) {
    asm volatile("ldmatrix.sync.aligned.m8n8.x4.shared.b16 {%0,%1,%2,%3}, [%4];"
                 : "=r"(r[0]), "=r"(r[1]), "=r"(r[2]), "=r"(r[3]) : "r"(addr));
}

// ---------------------------------------------------------------------------
// SMEM: K=32 chunks, DOUBLE-BUFFERED. Per buffer: A hi/lo + B hi/lo,
// each [128][40] bf16 (stride 80 B = 20 words: ldmatrix rows 20r..20r+3
// tile all 32 banks -> conflict-free). 2 x 40960 B = 81920 -> 2 blocks/SM.
// ---------------------------------------------------------------------------
#define STRB 80
#define IMGB (128 * STRB)        // 10240
#define OFF_AHI 0
#define OFF_ALO IMGB
#define OFF_BHI (2 * IMGB)
#define OFF_BLO (3 * IMGB)
#define BUFB (4 * IMGB)          // 40960
#define TC_SMEM_BYTES (2 * BUFB) // 81920

// Stage fp32 A chunk [128 x 32] -> bf16 hi/lo split into buffer
__device__ __forceinline__ void stage_A_f32(const float* __restrict__ A, int ldA,
                                            int row0, int nRows, int k0,
                                            char* buf, int tid) {
#pragma unroll
    for (int i = 0; i < 4; i++) {
        int g = tid + 256 * i;             // 1024 float4 = 128 rows x 8
        int r = g >> 3, c4 = g & 7;
        int grow = row0 + r;
        float4 v = {0.f, 0.f, 0.f, 0.f};
        if (grow < nRows)
            v = __ldg((const float4*)(A + (size_t)grow * ldA + k0) + c4);
        __nv_bfloat16 h0 = __float2bfloat16(v.x), h1 = __float2bfloat16(v.y);
        __nv_bfloat16 h2 = __float2bfloat16(v.z), h3 = __float2bfloat16(v.w);
        __nv_bfloat16 l0 = __float2bfloat16(v.x - __bfloat162float(h0));
        __nv_bfloat16 l1 = __float2bfloat16(v.y - __bfloat162float(h1));
        __nv_bfloat16 l2 = __float2bfloat16(v.z - __bfloat162float(h2));
        __nv_bfloat16 l3 = __float2bfloat16(v.w - __bfloat162float(h3));
        uint2 hu, lu;
        hu.x = packbf2(h0, h1); hu.y = packbf2(h2, h3);
        lu.x = packbf2(l0, l1); lu.y = packbf2(l2, l3);
        int off = r * STRB + c4 * 8;
        *(uint2*)(buf + OFF_AHI + off) = hu;
        *(uint2*)(buf + OFF_ALO + off) = lu;
    }
}

// Stage pre-split bf16 A chunk [128 x 32] (pure copy; global row = 256 bf16)
__device__ __forceinline__ void stage_A_bf16(const __nv_bfloat16* __restrict__ hi,
                                             const __nv_bfloat16* __restrict__ lo,
                                             int row0, int k0, char* buf, int tid) {
#pragma unroll
    for (int i = 0; i < 2; i++) {
        int idx = tid + 256 * i;           // 512 uint4 = 128 rows x 64 B
        int r = idx >> 2, kg = idx & 3;
        size_t gofs = (size_t)(row0 + r) * 256 + k0;
        uint4 h = __ldg((const uint4*)(hi + gofs) + kg);
        uint4 l = __ldg((const uint4*)(lo + gofs) + kg);
        int off = r * STRB + kg * 16;
        *(uint4*)(buf + OFF_AHI + off) = h;
        *(uint4*)(buf + OFF_ALO + off) = l;
    }
}

// Copy weight image K-chunk [128 n x 32 k] (image row = 128 bf16)
__device__ __forceinline__ void copy_B(const __nv_bfloat16* hi, const __nv_bfloat16* lo,
                                       int k0, char* buf, int tid) {
#pragma unroll
    for (int i = 0; i < 2; i++) {
        int idx = tid + 256 * i;
        int n = idx >> 2, kg = idx & 3;
        uint4 h = __ldg((const uint4*)(hi + n * 128 + k0) + kg);
        uint4 l = __ldg((const uint4*)(lo + n * 128 + k0) + kg);
        int off = n * STRB + kg * 16;
        *(uint4*)(buf + OFF_BHI + off) = h;
        *(uint4*)(buf + OFF_BLO + off) = l;
    }
}

// One K=32 chunk of HMMA (2 k-steps x 3 split terms), ldmatrix fragments
__device__ __forceinline__ void hmma_chunk(const char* buf, int warpM, int warpN,
                                           int lane, float acc[2][8][4]) {
    uint32_t aBase = (uint32_t)__cvta_generic_to_shared(buf + OFF_AHI);
    uint32_t bBase = (uint32_t)__cvta_generic_to_shared(buf + OFF_BHI);
    int aRow = warpM + ((lane >> 3) & 1) * 8 + (lane & 7);
    uint32_t aAddr = aBase + aRow * STRB + ((lane >> 4) & 1) * 16;
    int bRow = warpN + ((lane >> 4) & 1) * 8 + (lane & 7);
    uint32_t bAddr = bBase + bRow * STRB + ((lane >> 3) & 1) * 16;
    const uint32_t LOFF = IMGB;   // hi -> lo image offset

#pragma unroll
    for (int ks = 0; ks < 2; ks++) {
        unsigned ah[2][4], al[2][4];
        ldsm_x4(ah[0], aAddr);
        ldsm_x4(ah[1], aAddr + 16 * STRB);
        ldsm_x4(al[0], aAddr + LOFF);
        ldsm_x4(al[1], aAddr + LOFF + 16 * STRB);
#pragma unroll
        for (int ntp = 0; ntp < 4; ntp++) {
            unsigned bh[4], bl[4];
            ldsm_x4(bh, bAddr + ntp * (16 * STRB));
            ldsm_x4(bl, bAddr + ntp * (16 * STRB) + LOFF);
#pragma unroll
            for (int sub = 0; sub < 2; sub++) {
                int nt = ntp * 2 + sub;
                const unsigned* bhp = bh + sub * 2;
                const unsigned* blp = bl + sub * 2;
#pragma unroll
                for (int mt = 0; mt < 2; mt++) {
                    mma_bf16(acc[mt][nt], ah[mt], bhp);
                    mma_bf16(acc[mt][nt], ah[mt], blp);
                    mma_bf16(acc[mt][nt], al[mt], bhp);
                }
            }
        }
        aAddr += 32;
        bAddr += 32;
    }
}

// Epilogue to fp32 global (attn path)
__device__ __forceinline__ void epi_f32(const float acc[2][8][4],
                                        const float* __restrict__ bias,
                                        float* __restrict__ outBase, int ldOut,
                                        int row0, int nRows, bool relu,
                                        int warpM, int warpN, int lane) {
    int qr = lane >> 2, qc = lane & 3;
#pragma unroll
    for (int mt = 0; mt < 2; mt++) {
#pragma unroll
        for (int nt = 0; nt < 8; nt++) {
            int col = warpN + nt * 8 + qc * 2;
            float b0 = __ldg(bias + col), b1 = __ldg(bias + col + 1);
            int r0 = row0 + warpM + mt * 16 + qr;
#pragma unroll
            for (int half = 0; half < 2; half++) {
                int grow = r0 + half * 8;
                if (grow < nRows) {
                    float2 v;
                    v.x = acc[mt][nt][half * 2 + 0] + b0;
                    v.y = acc[mt][nt][half * 2 + 1] + b1;
                    if (relu) { v.x = fmaxf(v.x, 0.f); v.y = fmaxf(v.y, 0.f); }
                    *(float2*)(outBase + (size_t)grow * ldOut + col) = v;
                }
            }
        }
    }
}

// Epilogue to split-bf16 images (rows of 256, write at colOff + warp cols)
__device__ __forceinline__ void epi_bf16(const float acc[2][8][4],
                                         const float* __restrict__ bias,
                                         __nv_bfloat16* __restrict__ hiImg,
                                         __nv_bfloat16* __restrict__ loImg,
                                         int colOff, int row0, int nRows, bool relu,
                                         int warpM, int warpN, int lane) {
    int qr = lane >> 2, qc = lane & 3;
#pragma unroll
    for (int mt = 0; mt < 2; mt++) {
#pragma unroll
        for (int nt = 0; nt < 8; nt++) {
            int col = warpN + nt * 8 + qc * 2;
            float b0 = __ldg(bias + col), b1 = __ldg(bias + col + 1);
            int gcol = colOff + col;
            int r0 = row0 + warpM + mt * 16 + qr;
#pragma unroll
            for (int half = 0; half < 2; half++) {
                int grow = r0 + half * 8;
                if (grow < nRows) {
                    float vx = acc[mt][nt][half * 2 + 0] + b0;
                    float vy = acc[mt][nt][half * 2 + 1] + b1;
                    if (relu) { vx = fmaxf(vx, 0.f); vy = fmaxf(vy, 0.f); }
                    __nv_bfloat16 hx = __float2bfloat16(vx);
                    __nv_bfloat16 hy = __float2bfloat16(vy);
                    __nv_bfloat16 lx = __float2bfloat16(vx - __bfloat162float(hx));
                    __nv_bfloat16 ly = __float2bfloat16(vy - __bfloat162float(hy));
                    size_t o = (size_t)grow * 256 + gcol;
                    *(unsigned*)(hiImg + o) = packbf2(hx, hy);
                    *(unsigned*)(loImg + o) = packbf2(lx, ly);
                }
            }
        }
    }
}

// ---------------------------------------------------------------------------
// Setup kernels
// ---------------------------------------------------------------------------
__global__ void zero_counts_kernel() {
    int i = blockIdx.x * blockDim.x + threadIdx.x;
    if (i < NP_MAX) g_cntP[i] = 0;
    if (i < NHE_MAX) g_cntH[i] = 0;
    if (i == 0) { g_ovfH_cnt = 0; g_ovfP_cnt = 0; }
}

__global__ void prep_weights(const float* __restrict__ Wself,
                             const float* __restrict__ Wclu,
                             const float* __restrict__ Wf1,
                             const float* __restrict__ Wf2,
                             const float* __restrict__ Wh1) {
    int g = blockIdx.x * 256 + threadIdx.x;   // 163840 total
    int img = g >> 14;
    int e = g & 16383;
    int n = e >> 7, k = e & 127;
    float val;
    switch (img) {
        case 0: val = __ldg(Wself + k * 128 + n); break;
        case 1: val = __ldg(Wclu + k * 128 + n); break;
        case 2: val = __ldg(Wf1 + k * 256 + n); break;
        case 3: val = __ldg(Wf1 + (128 + k) * 256 + n); break;
        case 4: val = __ldg(Wf1 + k * 256 + 128 + n); break;
        case 5: val = __ldg(Wf1 + (128 + k) * 256 + 128 + n); break;
        case 6: val = __ldg(Wf2 + k * 128 + n); break;
        case 7: val = __ldg(Wf2 + (128 + k) * 128 + n); break;
        case 8: val = __ldg(Wh1 + ((n >> 6) * 128 + k) * 64 + (n & 63)); break;
        default: val = __ldg(Wh1 + ((2 + (n >> 6)) * 128 + k) * 64 + (n & 63)); break;
    }
    __nv_bfloat16 hi = __float2bfloat16(val);
    __nv_bfloat16 lo = __float2bfloat16(val - __bfloat162float(hi));
    g_wimg_hi[img][e] = hi;
    g_wimg_lo[img][e] = lo;
}

// ---------------------------------------------------------------------------
// Bucket fill
// ---------------------------------------------------------------------------
__global__ void bucket_fill(const int* __restrict__ pid, const int* __restrict__ hid,
                            const float* __restrict__ ew, int nE) {
    int e = blockIdx.x * 256 + threadIdx.x;
    if (e >= nE) return;
    int p = __ldg(pid + e);
    int h = __ldg(hid + e);
    float w = __ldg(ew + e);
    int s = atomicAdd(&g_cntH[h], 1);
    if (s < CAPH) g_bktH[h * CAPH + s] = make_int2(p, __float_as_int(w));
    else { int o = atomicAdd(&g_ovfH_cnt, 1); g_ovfH[o] = e; }
    s = atomicAdd(&g_cntP[p], 1);
    if (s < CAPP) g_bktP[p * CAPP + s] = make_int2(h, __float_as_int(w));
    else { int o = atomicAdd(&g_ovfP_cnt, 1); g_ovfP[o] = e; }
}

// ---------------------------------------------------------------------------
// Gather 1: he_feat[b] = sum over bucket of feat[pid] * w
// ---------------------------------------------------------------------------
__global__ void __launch_bounds__(128)
gather_he(const float* __restrict__ feat) {
    __shared__ int2 sbk[CAPH];
    int b = blockIdx.x, tid = threadIdx.x;
    int n = g_cntH[b];
    if (n > CAPH) n = CAPH;
    for (int i = tid; i < n; i += 128) sbk[i] = __ldg(&g_bktH[b * CAPH + i]);
    __syncthreads();

    float a0 = 0.f, a1 = 0.f, a2 = 0.f, a3 = 0.f;
    int i = 0;
    for (; i + 8 <= n; i += 8) {
        float f[8], w[8];
#pragma unroll
        for (int j = 0; j < 8; j++) {
            int2 e = sbk[i + j];
            f[j] = __ldg(feat + (size_t)e.x * 128 + tid);
            w[j] = __int_as_float(e.y);
        }
        a0 += f[0] * w[0] + f[4] * w[4];
        a1 += f[1] * w[1] + f[5] * w[5];
        a2 += f[2] * w[2] + f[6] * w[6];
        a3 += f[3] * w[3] + f[7] * w[7];
    }
    for (; i < n; i++) {
        int2 e = sbk[i];
        a0 += __ldg(feat + (size_t)e.x * 128 + tid) * __int_as_float(e.y);
    }
    g_he_feat[b * 128 + tid] = (a0 + a1) + (a2 + a3);
}

__global__ void ovf_replay_he(const float* __restrict__ feat,
                              const float* __restrict__ ew,
                              const int* __restrict__ pid,
                              const int* __restrict__ hid) {
    int total = g_ovfH_cnt * 32;
    for (int t = blockIdx.x * blockDim.x + threadIdx.x; t < total;
         t += gridDim.x * blockDim.x) {
        int i = t >> 5, lane = t & 31;
        int e = g_ovfH[i];
        int p = __ldg(pid + e), h = __ldg(hid + e);
        float w = __ldg(ew + e);
        float4 v = __ldg((const float4*)feat + p * 32 + lane);
        float* dst = g_he_feat + h * 128 + lane * 4;
        asm volatile("red.global.add.v4.f32 [%0], {%1,%2,%3,%4};"
                     :: "l"(dst), "f"(v.x * w), "f"(v.y * w), "f"(v.z * w), "f"(v.w * w)
                     : "memory");
    }
}

// ---------------------------------------------------------------------------
// Attention GEMM: g_h = relu(he_feat @ Wh1 + bh1)  (imgs 8,9; y = col half)
// ---------------------------------------------------------------------------
__global__ void __launch_bounds__(256, 2)
attn_gemm(const float* __restrict__ bh1, int nHE) {
    extern __shared__ char smem[];
    int tid = threadIdx.x;
    int wid = tid >> 5, lane = tid & 31;
    int warpM = (wid & 3) * 32, warpN = (wid >> 2) * 64;
    int y = blockIdx.y;
    int row0 = blockIdx.x * 128;

    float acc[2][8][4];
#pragma unroll
    for (int m = 0; m < 2; m++)
#pragma unroll
        for (int n = 0; n < 8; n++)
#pragma unroll
            for (int i = 0; i < 4; i++) acc[m][n][i] = 0.f;

    stage_A_f32(g_he_feat, 128, row0, nHE, 0, smem, tid);
    copy_B(g_wimg_hi[8 + y], g_wimg_lo[8 + y], 0, smem, tid);
    __syncthreads();
#pragma unroll
    for (int ch = 0; ch < 4; ch++) {
        char* cur = smem + (ch & 1) * BUFB;
        char* nxt = smem + ((ch + 1) & 1) * BUFB;
        if (ch < 3) {
            stage_A_f32(g_he_feat, 128, row0, nHE, (ch + 1) * 32, nxt, tid);
            copy_B(g_wimg_hi[8 + y], g_wimg_lo[8 + y], (ch + 1) * 32, nxt, tid);
        }
        hmma_chunk(cur, warpM, warpN, lane, acc);
        __syncthreads();
    }

    epi_f32(acc, bh1 + y * 128, g_h + y * 128, 256, row0, nHE, true,
            warpM, warpN, lane);
}

__global__ void __launch_bounds__(256)
attn_fuse(const float* __restrict__ Wh2, const float* __restrict__ bh2,
          const float* __restrict__ Wfuse, int nHE) {
    int wq = threadIdx.x >> 5, lane = threadIdx.x & 31;
    int he = blockIdx.x * 8 + wq;
    if (he >= nHE) return;
    const float* hr = g_h + (size_t)he * 256;
    float att = 0.f;
#pragma unroll
    for (int hh = 0; hh < 4; hh++) {
        float s = __ldg(hr + hh * 64 + lane) * __ldg(Wh2 + hh * 64 + lane)
                + __ldg(hr + hh * 64 + 32 + lane) * __ldg(Wh2 + hh * 64 + 32 + lane);
#pragma unroll
        for (int o = 16; o; o >>= 1) s += __shfl_xor_sync(0xffffffffu, s, o);
        float sg = 1.f / (1.f + expf(-(s + __ldg(bh2 + hh))));
        att += sg * __ldg(Wfuse + hh);
    }
    float4 f = __ldg((const float4*)(g_he_feat + (size_t)he * 128) + lane);
    f.x *= att; f.y *= att; f.z *= att; f.w *= att;
    *((float4*)(g_he_weighted + (size_t)he * 128) + lane) = f;
}

// ---------------------------------------------------------------------------
// Gather 2: cluster[p] = sum over bucket of he_weighted[hid] * w
// ---------------------------------------------------------------------------
__global__ void __launch_bounds__(128)
gather_p() {
    __shared__ int2 sbk[CAPP];
    int p = blockIdx.x, tid = threadIdx.x;
    int n = g_cntP[p];
    if (n > CAPP) n = CAPP;
    if (tid < n) sbk[tid] = __ldg(&g_bktP[p * CAPP + tid]);
    __syncthreads();

    float a0 = 0.f, a1 = 0.f, a2 = 0.f, a3 = 0.f;
    int i = 0;
    for (; i + 8 <= n; i += 8) {
        float f[8], w[8];
#pragma unroll
        for (int j = 0; j < 8; j++) {
            int2 e = sbk[i + j];
            f[j] = g_he_weighted[(size_t)e.x * 128 + tid];
            w[j] = __int_as_float(e.y);
        }
        a0 += f[0] * w[0] + f[4] * w[4];
        a1 += f[1] * w[1] + f[5] * w[5];
        a2 += f[2] * w[2] + f[6] * w[6];
        a3 += f[3] * w[3] + f[7] * w[7];
    }
    for (; i < n; i++) {
        int2 e = sbk[i];
        a0 += g_he_weighted[(size_t)e.x * 128 + tid] * __int_as_float(e.y);
    }
    g_cluster[p * 128 + tid] = (a0 + a1) + (a2 + a3);
}

__global__ void ovf_replay_p(const float* __restrict__ ew,
                             const int* __restrict__ pid,
                             const int* __restrict__ hid) {
    int total = g_ovfP_cnt * 32;
    for (int t = blockIdx.x * blockDim.x + threadIdx.x; t < total;
         t += gridDim.x * blockDim.x) {
        int i = t >> 5, lane = t & 31;
        int e = g_ovfP[i];
        int p = __ldg(pid + e), h = __ldg(hid + e);
        float w = __ldg(ew + e);
        float4 v = *(const float4*)(g_he_weighted + h * 128 + lane * 4);
        float* dst = g_cluster + p * 128 + lane * 4;
        asm volatile("red.global.add.v4.f32 [%0], {%1,%2,%3,%4};"
                     :: "l"(dst), "f"(v.x * w), "f"(v.y * w), "f"(v.z * w), "f"(v.w * w)
                     : "memory");
    }
}

// ---------------------------------------------------------------------------
// GEMM A: projections -> split-bf16 cat images (y=0 self half, y=1 clu half)
// ---------------------------------------------------------------------------
__global__ void __launch_bounds__(256, 2)
proj_tc(const float* __restrict__ feat,
        const float* __restrict__ bself, const float* __restrict__ bclu, int nP) {
    extern __shared__ char smem[];
    int tid = threadIdx.x;
    int wid = tid >> 5, lane = tid & 31;
    int warpM = (wid & 3) * 32, warpN = (wid >> 2) * 64;
    int y = blockIdx.y;
    int row0 = blockIdx.x * 128;
    const float* A = y ? g_cluster : feat;
    const float* bias = y ? bclu : bself;

    float acc[2][8][4];
#pragma unroll
    for (int m = 0; m < 2; m++)
#pragma unroll
        for (int n = 0; n < 8; n++)
#pragma unroll
            for (int i = 0; i < 4; i++) acc[m][n][i] = 0.f;

    stage_A_f32(A, 128, row0, nP, 0, smem, tid);
    copy_B(g_wimg_hi[y], g_wimg_lo[y], 0, smem, tid);
    __syncthreads();
#pragma unroll
    for (int ch = 0; ch < 4; ch++) {
        char* cur = smem + (ch & 1) * BUFB;
        char* nxt = smem + ((ch + 1) & 1) * BUFB;
        if (ch < 3) {
            stage_A_f32(A, 128, row0, nP, (ch + 1) * 32, nxt, tid);
            copy_B(g_wimg_hi[y], g_wimg_lo[y], (ch + 1) * 32, nxt, tid);
        }
        hmma_chunk(cur, warpM, warpN, lane, acc);
        __syncthreads();
    }

    epi_bf16(acc, bias, g_cat_hi, g_cat_lo, y * 128, row0, nP, false,
             warpM, warpN, lane);
}

// ---------------------------------------------------------------------------
// GEMM B: t1 = relu(cat @ Wf1 + bf1) -> split-bf16 t1 images. y = col half.
// ---------------------------------------------------------------------------
__global__ void __launch_bounds__(256, 2)
mlp1_tc(const float* __restrict__ bf1, int nP) {
    extern __shared__ char smem[];
    int tid = threadIdx.x;
    int wid = tid >> 5, lane = tid & 31;
    int warpM = (wid & 3) * 32, warpN = (wid >> 2) * 64;
    int y = blockIdx.y;
    int row0 = blockIdx.x * 128;
    int colOff = y * 128;

    float acc[2][8][4];
#pragma unroll
    for (int m = 0; m < 2; m++)
#pragma unroll
        for (int n = 0; n < 8; n++)
#pragma unroll
            for (int i = 0; i < 4; i++) acc[m][n][i] = 0.f;

    stage_A_bf16(g_cat_hi, g_cat_lo, row0, 0, smem, tid);
    copy_B(g_wimg_hi[2 + y * 2], g_wimg_lo[2 + y * 2], 0, smem, tid);
    __syncthreads();
#pragma unroll
    for (int ch = 0; ch < 8; ch++) {
        char* cur = smem + (ch & 1) * BUFB;
        char* nxt = smem + ((ch + 1) & 1) * BUFB;
        if (ch < 7) {
            int kg = (ch + 1) * 32;
            stage_A_bf16(g_cat_hi, g_cat_lo, row0, kg, nxt, tid);
            int img = 2 + y * 2 + (kg >> 7);
            copy_B(g_wimg_hi[img], g_wimg_lo[img], kg & 127, nxt, tid);
        }
        hmma_chunk(cur, warpM, warpN, lane, acc);
        __syncthreads();
    }

    epi_bf16(acc, bf1 + colOff, g_t1_hi, g_t1_lo, colOff, row0, nP, true,
             warpM, warpN, lane);
}

// ---------------------------------------------------------------------------
// GEMM C: t2 = relu(t1 @ Wf2 + bf2); fw = softmax(t2@Wf3+bf3);
//         out = relu(self_f*fw0 + clu_f*fw1 + feat)
// ---------------------------------------------------------------------------
#define LDT2 129
__global__ void __launch_bounds__(256, 2)
mlp2_tc(const float* __restrict__ feat,
        const float* __restrict__ bf2,
        const float* __restrict__ Wf3, const float* __restrict__ bf3,
        float* __restrict__ out, int nP) {
    extern __shared__ char smem[];
    int tid = threadIdx.x;
    int wid = tid >> 5, lane = tid & 31;
    int warpM = (wid & 3) * 32, warpN = (wid >> 2) * 64;
    int row0 = blockIdx.x * 128;

    float acc[2][8][4];
#pragma unroll
    for (int m = 0; m < 2; m++)
#pragma unroll
        for (int n = 0; n < 8; n++)
#pragma unroll
            for (int i = 0; i < 4; i++) acc[m][n][i] = 0.f;

    stage_A_bf16(g_t1_hi, g_t1_lo, row0, 0, smem, tid);
    copy_B(g_wimg_hi[6], g_wimg_lo[6], 0, smem, tid);
    __syncthreads();
#pragma unroll
    for (int ch = 0; ch < 8; ch++) {
        char* cur = smem + (ch & 1) * BUFB;
        char* nxt = smem + ((ch + 1) & 1) * BUFB;
        if (ch < 7) {
            int kg = (ch + 1) * 32;
            stage_A_bf16(g_t1_hi, g_t1_lo, row0, kg, nxt, tid);
            int img = 6 + (kg >> 7);
            copy_B(g_wimg_hi[img], g_wimg_lo[img], kg & 127, nxt, tid);
        }
        hmma_chunk(cur, warpM, warpN, lane, acc);
        __syncthreads();
    }
    __syncthreads();

    float* sT2 = (float*)smem;                     // 128*129*4 = 66048 <= 81920
    float* sFW = (float*)(smem + 128 * LDT2 * 4);
    {
        int qr = lane >> 2, qc = lane & 3;
#pragma unroll
        for (int mt = 0; mt < 2; mt++) {
#pragma unroll
            for (int nt = 0; nt < 8; nt++) {
                int col = warpN + nt * 8 + qc * 2;
                float b0 = __ldg(bf2 + col), b1 = __ldg(bf2 + col + 1);
#pragma unroll
                for (int half = 0; half < 2; half++) {
                    int r = warpM + mt * 16 + qr + half * 8;
                    sT2[r * LDT2 + col] =
                        fmaxf(acc[mt][nt][half * 2 + 0] + b0, 0.f);
                    sT2[r * LDT2 + col + 1] =
                        fmaxf(acc[mt][nt][half * 2 + 1] + b1, 0.f);
                }
            }
        }
    }
    __syncthreads();

    if (tid < 128) {
        float l0 = __ldg(bf3), l1 = __ldg(bf3 + 1);
        const float* trow = sT2 + tid * LDT2;
#pragma unroll 8
        for (int k = 0; k < 128; k++) {
            float v = trow[k];
            l0 += v * __ldg(Wf3 + 2 * k);
            l1 += v * __ldg(Wf3 + 2 * k + 1);
        }
        float w0 = 1.f / (1.f + expf(l1 - l0));
        sFW[2 * tid] = w0;
        sFW[2 * tid + 1] = 1.f - w0;
    }
    __syncthreads();

    // final fuse: self/clu reconstructed as hi + lo
    for (int idx = tid; idx < 128 * 32; idx += 256) {
        int r = idx >> 5, c4 = idx & 31;
        int grow = row0 + r;
        if (grow < nP) {
            float w0 = sFW[2 * r], w1 = sFW[2 * r + 1];
            size_t so = (size_t)grow * 256 + c4 * 4;
            size_t co = so + 128;
            uint2 sh = *(const uint2*)(g_cat_hi + so);
            uint2 sl = *(const uint2*)(g_cat_lo + so);
            uint2 ch = *(const uint2*)(g_cat_hi + co);
            uint2 cl = *(const uint2*)(g_cat_lo + co);
            const __nv_bfloat16* shp = (const __nv_bfloat16*)&sh;
            const __nv_bfloat16* slp = (const __nv_bfloat16*)&sl;
            const __nv_bfloat16* chp = (const __nv_bfloat16*)&ch;
            const __nv_bfloat16* clp = (const __nv_bfloat16*)&cl;
            float4 f = __ldg((const float4*)(feat + (size_t)grow * 128) + c4);
            float4 o;
            float s0 = __bfloat162float(shp[0]) + __bfloat162float(slp[0]);
            float s1 = __bfloat162float(shp[1]) + __bfloat162float(slp[1]);
            float s2 = __bfloat162float(shp[2]) + __bfloat162float(slp[2]);
            float s3 = __bfloat162float(shp[3]) + __bfloat162float(slp[3]);
            float c0 = __bfloat162float(chp[0]) + __bfloat162float(clp[0]);
            float c1 = __bfloat162float(chp[1]) + __bfloat162float(clp[1]);
            float c2 = __bfloat162float(chp[2]) + __bfloat162float(clp[2]);
            float c3 = __bfloat162float(chp[3]) + __bfloat162float(clp[3]);
            o.x = fmaxf(s0 * w0 + c0 * w1 + f.x, 0.f);
            o.y = fmaxf(s1 * w0 + c1 * w1 + f.y, 0.f);
            o.z = fmaxf(s2 * w0 + c2 * w1 + f.z, 0.f);
            o.w = fmaxf(s3 * w0 + c3 * w1 + f.w, 0.f);
            *(float4*)(out + (size_t)grow * 128 + c4 * 4) = o;
        }
    }
}

// ---------------------------------------------------------------------------
extern "C" void kernel_launch(void* const* d_in, const int* in_sizes, int n_in,
                              void* d_out, int out_size) {
    const float* feat   = (const float*)d_in[0];
    const float* edge_w = (const float*)d_in[1];
    const float* Wself  = (const float*)d_in[2];
    const float* bself  = (const float*)d_in[3];
    const float* Wclu   = (const float*)d_in[4];
    const float* bclu   = (const float*)d_in[5];
    const float* Wh1    = (const float*)d_in[6];
    const float* bh1    = (const float*)d_in[7];
    const float* Wh2    = (const float*)d_in[8];
    const float* bh2    = (const float*)d_in[9];
    const float* Wfuse  = (const float*)d_in[10];
    const float* Wf1    = (const float*)d_in[11];
    const float* bf1    = (const float*)d_in[12];
    const float* Wf2    = (const float*)d_in[13];
    const float* bf2    = (const float*)d_in[14];
    const float* Wf3    = (const float*)d_in[15];
    const float* bf3    = (const float*)d_in[16];
    const int* edge_pid = (const int*)d_in[17];
    const int* edge_hid = (const int*)d_in[18];

    int nP  = in_sizes[0] / 128;
    int nE  = in_sizes[17];
    int nHE = NHE_MAX;

    zero_counts_kernel<<<(NP_MAX + 255) / 256, 256>>>();
    prep_weights<<<640, 256>>>(Wself, Wclu, Wf1, Wf2, Wh1);
    bucket_fill<<<(nE + 255) / 256, 256>>>(edge_pid, edge_hid, edge_w, nE);

    gather_he<<<nHE, 128>>>(feat);
    ovf_replay_he<<<64, 256>>>(feat, edge_w, edge_pid, edge_hid);

    int nBlkH = (nHE + 127) / 128;
    cudaFuncSetAttribute(attn_gemm, cudaFuncAttributeMaxDynamicSharedMemorySize,
                         TC_SMEM_BYTES);
    attn_gemm<<<dim3(nBlkH, 2), 256, TC_SMEM_BYTES>>>(bh1, nHE);
    attn_fuse<<<(nHE + 7) / 8, 256>>>(Wh2, bh2, Wfuse, nHE);

    gather_p<<<nP, 128>>>();
    ovf_replay_p<<<64, 256>>>(edge_w, edge_pid, edge_hid);

    int nBlk = (nP + 127) / 128;
    cudaFuncSetAttribute(proj_tc, cudaFuncAttributeMaxDynamicSharedMemorySize,
                         TC_SMEM_BYTES);
    proj_tc<<<dim3(nBlk, 2), 256, TC_SMEM_BYTES>>>(feat, bself, bclu, nP);

    cudaFuncSetAttribute(mlp1_tc, cudaFuncAttributeMaxDynamicSharedMemorySize,
                         TC_SMEM_BYTES);
    mlp1_tc<<<dim3(nBlk, 2), 256, TC_SMEM_BYTES>>>(bf1, nP);

    cudaFuncSetAttribute(mlp2_tc, cudaFuncAttributeMaxDynamicSharedMemorySize,
                         TC_SMEM_BYTES);
    mlp2_tc<<<nBlk, 256, TC_SMEM_BYTES>>>(feat, bf2, Wf3, bf3, (float*)d_out, nP);
}